// round 7
// baseline (speedup 1.0000x reference)
#include <cuda_runtime.h>
#include <cuda_fp16.h>
#include <cstdint>

#define BB 256
#define TT 256
#define DD 80
#define HH 512
#define GG 2048
#define NBLK 128
#define CS 136                 // h chunk smem stride (halves)

// ---------------- device scratch ----------------
__device__ __align__(16) __half g_h16[2][(size_t)BB*HH]; // [parity]
__device__ __align__(16) __half g_txh[(size_t)BB*TT*DD];
__device__ float g_Wcomb[(size_t)GG*HH];
__device__ float g_bias_enc[GG];
__device__ float g_bcomb[GG];
__device__ float g_quant[BB*HH];
__device__ float g_hA[BB*HH];
__device__ float g_tmpT[DD*BB];
__device__ float g_corr[(size_t)BB*GG];
__device__ float g_lossp[BB];
__device__ int   g_idx[BB];
__device__ float g_Hbuf[(size_t)TT*BB*HH];
__device__ unsigned g_flagE[16];   // [rg][chunk]
__device__ unsigned g_flagD[16];

// ---------------- helpers ----------------
__device__ __forceinline__ unsigned long long dupf(float v){
    unsigned long long r; asm("mov.b64 %0, {%1,%1};" : "=l"(r) : "f"(v)); return r;
}
__device__ __forceinline__ float2 ull2f(unsigned long long v){
    float2 r; asm("mov.b64 {%0,%1}, %2;" : "=f"(r.x), "=f"(r.y) : "l"(v)); return r;
}
__device__ __forceinline__ void ffma2(unsigned long long& d, unsigned long long a, unsigned long long b){
    asm("fma.rn.f32x2 %0, %1, %2, %0;" : "+l"(d) : "l"(a), "l"(b));
}
__device__ __forceinline__ float sigf(float x){ return 1.f/(1.f + __expf(-x)); }
__device__ __forceinline__ float tanh_f(float x){ return 2.f/(1.f + __expf(-2.f*x)) - 1.f; }

__device__ __forceinline__ void cpa16s(uint32_t dst, const void* src){
    asm volatile("cp.async.cg.shared.global [%0], [%1], 16;" :: "r"(dst), "l"(src));
}
__device__ __forceinline__ void cpa_commit(){ asm volatile("cp.async.commit_group;" ::: "memory"); }
__device__ __forceinline__ void cpa_wait0(){ asm volatile("cp.async.wait_group 0;" ::: "memory"); }
__device__ __forceinline__ void cpa_wait1(){ asm volatile("cp.async.wait_group 1;" ::: "memory"); }

__device__ __forceinline__ void ldsm4(uint32_t* r, uint32_t addr){
    asm volatile("ldmatrix.sync.aligned.m8n8.x4.shared.b16 {%0,%1,%2,%3}, [%4];"
        : "=r"(r[0]), "=r"(r[1]), "=r"(r[2]), "=r"(r[3]) : "r"(addr));
}
__device__ __forceinline__ void hmma(float* c, const uint32_t* a, const uint32_t* b){
    asm volatile("mma.sync.aligned.m16n8k16.row.col.f32.f16.f16.f32 "
        "{%0,%1,%2,%3}, {%4,%5,%6,%7}, {%8,%9}, {%0,%1,%2,%3};"
        : "+f"(c[0]), "+f"(c[1]), "+f"(c[2]), "+f"(c[3])
        : "r"(a[0]), "r"(a[1]), "r"(a[2]), "r"(a[3]), "r"(b[0]), "r"(b[1]));
}

__device__ __forceinline__ void spin_ge(unsigned* p, unsigned tgt){
    unsigned v;
    do {
        asm volatile("ld.acquire.gpu.u32 %0, [%1];" : "=r"(v) : "l"(p) : "memory");
    } while (v < tgt);
}
__device__ __forceinline__ void post_flag(unsigned* p){
    asm volatile("red.release.gpu.global.add.u32 [%0], %1;" :: "l"(p), "r"(1u) : "memory");
}

// 2-term MMA over one chunk: acc[gate][4]
template<int NK, int SW>
__device__ __forceinline__ void mma_loop(float acc[4][4], uint32_t aA,
                                         uint32_t bH, uint32_t bL){
    #pragma unroll
    for (int kk = 0; kk < NK; kk++){
        uint32_t ah[4], bh0[4], bh1[4], bl0[4], bl1[4];
        ldsm4(ah,  aA + kk*32);
        ldsm4(bh0, bH + kk*32);
        ldsm4(bh1, bH + 16*SW*2 + kk*32);
        ldsm4(bl0, bL + kk*32);
        ldsm4(bl1, bL + 16*SW*2 + kk*32);
        hmma(acc[0], ah, bh0);   hmma(acc[1], ah, bh0+2);
        hmma(acc[2], ah, bh1);   hmma(acc[3], ah, bh1+2);
        hmma(acc[0], ah, bl0);   hmma(acc[1], ah, bl0+2);
        hmma(acc[2], ah, bl1);   hmma(acc[3], ah, bl1+2);
    }
}

// ---------------- prep kernels ----------------
__global__ void k_bias(const float* __restrict__ ebi, const float* __restrict__ ebh,
                       const float* __restrict__ dbi, const float* __restrict__ dbh,
                       const float* __restrict__ dWih, const float* __restrict__ fcb){
    int n = blockIdx.x*blockDim.x + threadIdx.x;
    if (n < GG){
        g_bias_enc[n] = ebi[n] + ebh[n];
        float b = dbi[n] + dbh[n];
        const float* w = dWih + (size_t)n*DD;
        #pragma unroll 4
        for (int d = 0; d < DD; d++) b += fcb[d]*w[d];
        g_bcomb[n] = b;
    }
}

__global__ void k_wcomb(const float* __restrict__ dWih, const float* __restrict__ dWhh,
                        const float* __restrict__ fcW){
    __shared__ float sf[DD][64];
    __shared__ float sw[32][DD];
    int nt = blockIdx.x >> 3, kt = blockIdx.x & 7;
    int n0 = nt*32, k0 = kt*64;
    int tid = threadIdx.x;
    for (int idx = tid; idx < DD*64; idx += 256){
        int d = idx >> 6, kk = idx & 63;
        sf[d][kk] = fcW[(size_t)d*HH + k0 + kk];
    }
    for (int idx = tid; idx < 32*DD; idx += 256){
        int nn = idx / DD, d = idx % DD;
        sw[nn][d] = dWih[(size_t)(n0+nn)*DD + d];
    }
    __syncthreads();
    int nn = tid >> 3, kb = (tid & 7)*8;
    float a[8];
    #pragma unroll
    for (int i = 0; i < 8; i++) a[i] = dWhh[(size_t)(n0+nn)*HH + k0 + kb + i];
    for (int d = 0; d < DD; d++){
        float w = sw[nn][d];
        #pragma unroll
        for (int i = 0; i < 8; i++) a[i] += w * sf[d][kb+i];
    }
    #pragma unroll
    for (int i = 0; i < 8; i++) g_Wcomb[(size_t)(n0+nn)*HH + k0 + kb + i] = a[i];
}

__global__ void k_tx(const float* __restrict__ traj){
    if (blockIdx.x == 0 && threadIdx.x < 32){
        if (threadIdx.x < 16) g_flagE[threadIdx.x] = 0u;
        else                  g_flagD[threadIdx.x - 16] = 0u;
    }
    size_t N = (size_t)BB*TT*DD;
    for (size_t i = (size_t)blockIdx.x*blockDim.x + threadIdx.x; i < N; i += (size_t)gridDim.x*blockDim.x)
        g_txh[i] = __float2half_rn(traj[i]);
}

__global__ void k_x1(const float* __restrict__ fcW, const float* __restrict__ fcb){
    int b = blockIdx.x, tid = threadIdx.x;
    __shared__ float qs[HH];
    qs[tid]       = g_quant[(size_t)b*HH + tid];
    qs[tid + 256] = g_quant[(size_t)b*HH + tid + 256];
    __syncthreads();
    if (tid < DD){
        const float* w = fcW + (size_t)tid*HH;
        float s = fcb[tid];
        for (int k = 0; k < HH; k++) s += w[k]*qs[k];
        g_tmpT[tid*BB + b] = s;
    }
}

__global__ void k_corr(const float* __restrict__ dWih){
    int n = blockIdx.x, b = threadIdx.x;
    __shared__ float wd[DD];
    if (b < DD) wd[b] = dWih[(size_t)n*DD + b];
    __syncthreads();
    float s = 0.f;
    #pragma unroll 4
    for (int d = 0; d < DD; d++) s += wd[d] * g_tmpT[d*BB + b];
    g_corr[(size_t)b*GG + n] = s;
}

__global__ void k_decprep(){
    int i = blockIdx.x*blockDim.x + threadIdx.x;
    if (i < BB*HH) g_h16[0][i] = __float2half_rn(g_quant[i]);
}

// ---------------- persistent recurrent kernel ----------------
// Block: 64 batch rows x 64 gate-cols (16 j x 4 gates). 8 warps = 4 M x 2 N.
// Cross-block sync: per-(rowgroup, k-chunk) release/acquire counters.
template<bool ENC>
__global__ void __launch_bounds__(256, 1) k_rnn(const float* __restrict__ eWih,
                                                const float* __restrict__ eWhh){
    extern __shared__ __half smh[];
    constexpr int SW = ENC ? 600 : 520;
    constexpr int KW = ENC ? 592 : 512;
    constexpr int NC = ENC ? 5 : 4;
    const uint32_t WREG = (uint32_t)(64*SW*2);   // bytes per W copy
    const uint32_t HS_OFF = 2u*WREG;
    const uint32_t BUFB = (uint32_t)(64*CS*2);

    const int tid = threadIdx.x;
    const int wid = tid >> 5, lane = tid & 31;
    const int wm = wid & 3, wn = wid >> 2;
    const int rg = blockIdx.x >> 5, cg = blockIdx.x & 31;
    const int row0 = rg*64, j0 = cg*16;
    const uint32_t smb = (uint32_t)__cvta_generic_to_shared(smh);
    unsigned* flg  = (ENC ? g_flagE : g_flagD) + rg*4;
    unsigned* mypf = flg + (cg >> 3);

    // ---- W fill (hi/lo split), resident all steps ----
    for (int idx = tid; idx < 64*KW; idx += 256){
        int br = idx / KW, k = idx - br*KW;
        int n = ((br >> 3) & 3)*HH + j0 + (br >> 5)*8 + (br & 7);
        float v;
        if (ENC) v = (k < HH) ? eWhh[(size_t)n*HH + k] : eWih[(size_t)n*DD + k - HH];
        else     v = g_Wcomb[(size_t)n*HH + k];
        __half h = __float2half_rn(v);
        smh[br*SW + k] = h;
        smh[64*SW + br*SW + k] = __float2half_rn(v - __half2float(h));
    }

    const int j0w = j0 + wn*8;
    const int jj = (lane & 3)*2;
    const int rbase = row0 + wm*16 + (lane >> 2);
    float bias[4][2], corr[2][4][2];
    #pragma unroll
    for (int q = 0; q < 4; q++)
        #pragma unroll
        for (int e = 0; e < 2; e++){
            bias[q][e] = ENC ? g_bias_enc[q*HH + j0w + jj + e] : g_bcomb[q*HH + j0w + jj + e];
            if (!ENC){
                corr[0][q][e] = g_corr[(size_t)rbase*GG + q*HH + j0w + jj + e];
                corr[1][q][e] = g_corr[(size_t)(rbase+8)*GG + q*HH + j0w + jj + e];
            }
        }
    float cst[2][2] = {{0.f,0.f},{0.f,0.f}};

    const uint32_t laneA = (uint32_t)((wm*16 + (lane & 15))*CS + (lane >> 4)*8)*2;
    const uint32_t laneB = (uint32_t)(((lane & 7) + ((lane >> 4) & 1)*8 + wn*32)*SW + ((lane >> 3) & 1)*8)*2;

    // stage chunk c of step t into buffer buf
    auto stage = [&](int buf, int c, int t){
        uint32_t dst = smb + HS_OFF + (uint32_t)buf*BUFB;
        if (ENC && c == 0){
            #pragma unroll
            for (int i = 0; i < 3; i++){
                int u = tid + i*256;
                if (u < 640){
                    int row = u/10, seg = u - row*10;
                    cpa16s(dst + (uint32_t)(row*CS + seg*8)*2,
                           g_txh + ((size_t)(row0+row)*TT + t)*DD + seg*8);
                }
            }
        } else {
            const __half* src = g_h16[t & 1];
            int kb = ENC ? (c-1)*128 : c*128;
            #pragma unroll
            for (int i = 0; i < 4; i++){
                int u = tid + i*256;
                int row = u >> 4, seg = u & 15;
                cpa16s(dst + (uint32_t)(row*CS + seg*8)*2,
                       src + (size_t)(row0+row)*HH + kb + seg*8);
            }
        }
        cpa_commit();
    };

    __syncthreads();

    for (int t = 0; t < TT; t++){
        const unsigned tgt = 8u*(unsigned)t;
        const int nc = (ENC && t == 0) ? 1 : NC;

        // ---- prologue staging (flag-gated per chunk) ----
        if (ENC){
            stage(0, 0, t);   // x chunk: no cross-block dependency
            if (nc > 1){
                if (t > 0 && tid == 0) spin_ge(flg + 0, tgt);
                __syncthreads();
                stage(1, 1, t);
            }
        } else {
            if (t > 0 && tid == 0){ spin_ge(flg + 0, tgt); spin_ge(flg + 1, tgt); }
            __syncthreads();
            stage(0, 0, t); stage(1, 1, t);
        }

        float acc[4][4];
        #pragma unroll
        for (int q = 0; q < 4; q++)
            #pragma unroll
            for (int i = 0; i < 4; i++) acc[q][i] = 0.f;

        for (int c = 0; c < nc; c++){
            if (c + 2 < nc && t > 0 && tid == 0)
                spin_ge(flg + (ENC ? c+1 : c+2), tgt);
            if (c < nc-1) cpa_wait1(); else cpa_wait0();
            __syncthreads();
            if (c + 2 < nc) stage((c+2)%3, c+2, t);
            {
                uint32_t aA = smb + HS_OFF + (uint32_t)(c%3)*BUFB + laneA;
                int koff = (ENC && c == 0) ? 512 : (ENC ? (c-1)*128 : c*128);
                uint32_t bH = smb + laneB + (uint32_t)koff*2;
                uint32_t bL = bH + WREG;
                if (ENC && c == 0) mma_loop<5, SW>(acc, aA, bH, bL);
                else               mma_loop<8, SW>(acc, aA, bH, bL);
            }
        }
        __syncthreads();

        // ---- epilogue: gates -> h, publish, post flag ----
        {
            const int nimg = (t+1) & 1;
            float hvf[2][2];
            #pragma unroll
            for (int p = 0; p < 2; p++){
                #pragma unroll
                for (int e = 0; e < 2; e++){
                    float gi = acc[0][p*2+e] + bias[0][e];
                    float gf = acc[1][p*2+e] + bias[1][e];
                    float gg = acc[2][p*2+e] + bias[2][e];
                    float go = acc[3][p*2+e] + bias[3][e];
                    if (!ENC && t == 0){
                        gi -= corr[p][0][e]; gf -= corr[p][1][e];
                        gg -= corr[p][2][e]; go -= corr[p][3][e];
                    }
                    float cn = sigf(gf)*cst[p][e] + sigf(gi)*tanh_f(gg);
                    cst[p][e] = cn;
                    hvf[p][e] = sigf(go)*tanh_f(cn);
                }
                int r = rbase + p*8;
                __half h0 = __float2half_rn(hvf[p][0]);
                __half h1 = __float2half_rn(hvf[p][1]);
                uint32_t uh = (uint32_t)__half_as_ushort(h0) | ((uint32_t)__half_as_ushort(h1) << 16);
                *(uint32_t*)&g_h16[nimg][(size_t)r*HH + j0w + jj] = uh;
            }
            __syncthreads();
            if (tid == 0) post_flag(mypf);
            // secondary outputs (off the sync critical path)
            #pragma unroll
            for (int p = 0; p < 2; p++){
                int r = rbase + p*8;
                if (ENC){
                    if (t == TT-1){
                        g_hA[(size_t)r*HH + j0w + jj]     = hvf[p][0];
                        g_hA[(size_t)r*HH + j0w + jj + 1] = hvf[p][1];
                    }
                } else {
                    float2 f2; f2.x = hvf[p][0]; f2.y = hvf[p][1];
                    *(float2*)&g_Hbuf[((size_t)t*BB + r)*HH + j0w + jj] = f2;
                }
            }
        }
    }
}

// ---------------- VQ ----------------
__global__ void k_vq(const float* __restrict__ emb){
    int b = blockIdx.x, tid = threadIdx.x;
    __shared__ float zs[HH];
    __shared__ float rs[256];
    __shared__ int   rk[256];
    zs[tid]       = g_hA[(size_t)b*HH + tid];
    zs[tid + 256] = g_hA[(size_t)b*HH + tid + 256];
    __syncthreads();
    float bestS = 3.4e38f; int bestK = 0;
    #pragma unroll
    for (int kq = 0; kq < 2; kq++){
        int k = tid + kq*256;
        const float* e = emb + (size_t)k*HH;
        float s = 0.f, dt = 0.f;
        for (int jj = 0; jj < HH; jj++){ float ev = e[jj]; s += ev*ev; dt += ev*zs[jj]; }
        float score = s - 2.f*dt;
        if (score < bestS || (score == bestS && k < bestK)){ bestS = score; bestK = k; }
    }
    rs[tid] = bestS; rk[tid] = bestK;
    __syncthreads();
    for (int s = 128; s > 0; s >>= 1){
        if (tid < s){
            if (rs[tid+s] < rs[tid] || (rs[tid+s] == rs[tid] && rk[tid+s] < rk[tid])){
                rs[tid] = rs[tid+s]; rk[tid] = rk[tid+s];
            }
        }
        __syncthreads();
    }
    int idx = rk[0];
    if (tid == 0) g_idx[b] = idx;
    float lp = 0.f;
    #pragma unroll
    for (int kq = 0; kq < 2; kq++){
        int jj = tid + kq*256;
        float q = emb[(size_t)idx*HH + jj];
        g_quant[(size_t)b*HH + jj] = q;
        float dz = q - zs[jj];
        lp += dz*dz;
    }
    __syncthreads();
    rs[tid] = lp;
    __syncthreads();
    for (int s = 128; s > 0; s >>= 1){
        if (tid < s) rs[tid] += rs[tid+s];
        __syncthreads();
    }
    if (tid == 0) g_lossp[b] = rs[0];
}

__global__ void k_vqfinish(float* __restrict__ out){
    const size_t OFF = (size_t)BB*TT*DD;
    int tid = threadIdx.x;
    if (tid == 0){
        float tot = 0.f;
        for (int i = 0; i < BB; i++) tot += g_lossp[i];
        out[OFF] = 1.25f * tot / (float)(BB*HH);
    }
    out[OFF + 1 + tid] = (float)g_idx[tid];
}

// ---------------- recon head ----------------
__device__ __forceinline__ void stage_h32r(float hsb[32][68], const float* __restrict__ src, int stride){
    int kk = threadIdx.x & 31, rb = threadIdx.x >> 5;
    #pragma unroll
    for (int i = 0; i < 8; i++)
        hsb[kk][rb + i*8] = src[(size_t)(rb + i*8)*stride + kk];
}

__global__ void __launch_bounds__(256) k_recon(const float* __restrict__ fcW,
                                               const float* __restrict__ fcb,
                                               float* __restrict__ out){
    __shared__ __align__(16) float hsb[32][68];
    __shared__ unsigned long long wsd[32][DD];
    int t = blockIdx.x;
    int b0 = blockIdx.y * 64;
    int tid = threadIdx.x;
    int txd = tid & 15, tyb = tid >> 4;

    unsigned long long acc[5][2];
    #pragma unroll
    for (int s = 0; s < 5; s++){ acc[s][0] = 0ull; acc[s][1] = 0ull; }

    for (int c = 0; c < 16; c++){
        __syncthreads();
        stage_h32r(hsb, g_Hbuf + ((size_t)t*BB + b0)*HH + c*32, HH);
        {
            int kk = tid & 31, db = tid >> 5;
            #pragma unroll
            for (int i = 0; i < 10; i++){
                int d = db + i*8;
                wsd[kk][d] = dupf(fcW[(size_t)d*HH + c*32 + kk]);
            }
        }
        __syncthreads();
        #pragma unroll
        for (int kk = 0; kk < 32; kk++){
            ulonglong2 hp = *(const ulonglong2*)&hsb[kk][tyb*4];
            #pragma unroll
            for (int s = 0; s < 5; s++){
                unsigned long long w = wsd[kk][txd + 16*s];
                ffma2(acc[s][0], hp.x, w);
                ffma2(acc[s][1], hp.y, w);
            }
        }
    }
    #pragma unroll
    for (int s = 0; s < 5; s++){
        int d = txd + 16*s;
        float bv = fcb[d];
        #pragma unroll
        for (int p = 0; p < 2; p++){
            float2 v = ull2f(acc[s][p]);
            int b = b0 + tyb*4 + p*2;
            out[((size_t)b*TT + t)*DD + d]     = v.x + bv;
            out[((size_t)(b+1)*TT + t)*DD + d] = v.y + bv;
        }
    }
}

// ---------------- launcher ----------------
extern "C" void kernel_launch(void* const* d_in, const int* in_sizes, int n_in,
                              void* d_out, int out_size){
    (void)in_sizes; (void)n_in; (void)out_size;
    const float* traj = (const float*)d_in[0];
    const float* eWih = (const float*)d_in[2];
    const float* eWhh = (const float*)d_in[3];
    const float* ebi  = (const float*)d_in[4];
    const float* ebh  = (const float*)d_in[5];
    const float* emb  = (const float*)d_in[6];
    const float* dWih = (const float*)d_in[7];
    const float* dWhh = (const float*)d_in[8];
    const float* dbi  = (const float*)d_in[9];
    const float* dbh  = (const float*)d_in[10];
    const float* fcW  = (const float*)d_in[11];
    const float* fcb  = (const float*)d_in[12];
    float* out = (float*)d_out;

    const int SME = (2*64*600 + 3*64*CS)*2;   // 205824 B
    const int SMD = (2*64*520 + 3*64*CS)*2;   // 185344 B
    cudaFuncSetAttribute(k_rnn<true>,  cudaFuncAttributeMaxDynamicSharedMemorySize, SME);
    cudaFuncSetAttribute(k_rnn<false>, cudaFuncAttributeMaxDynamicSharedMemorySize, SMD);

    k_bias<<<8, 256>>>(ebi, ebh, dbi, dbh, dWih, fcb);
    k_wcomb<<<512, 256>>>(dWih, dWhh, fcW);
    k_tx<<<1024, 256>>>(traj);
    k_rnn<true><<<NBLK, 256, SME>>>(eWih, eWhh);   // launch #4 -> ncu capture slot
    k_vq<<<BB, 256>>>(emb);
    k_vqfinish<<<1, 256>>>(out);
    k_x1<<<BB, 256>>>(fcW, fcb);
    k_corr<<<GG, 256>>>(dWih);
    k_decprep<<<512, 256>>>();
    k_rnn<false><<<NBLK, 256, SMD>>>(eWih, eWhh);
    k_recon<<<dim3(TT, 4), 256>>>(fcW, fcb, out);
}

// round 9
// speedup vs baseline: 1.0243x; 1.0243x over previous
#include <cuda_runtime.h>
#include <cuda_fp16.h>
#include <cstdint>

#define BB 256
#define TT 256
#define DD 80
#define HH 512
#define GG 2048
#define NBLK 128

// ---------------- device scratch ----------------
__device__ __align__(16) __half g_h16[2][(size_t)BB*HH]; // [parity]
__device__ __align__(16) __half g_txh[(size_t)BB*TT*DD];
__device__ float g_Wcomb[(size_t)GG*HH];
__device__ float g_bias_enc[GG];
__device__ float g_bcomb[GG];
__device__ float g_quant[BB*HH];
__device__ float g_hA[BB*HH];
__device__ float g_tmpT[DD*BB];
__device__ float g_corr[(size_t)BB*GG];
__device__ float g_lossp[BB];
__device__ int   g_idx[BB];
__device__ float g_Hbuf[(size_t)TT*BB*HH];
__device__ unsigned g_flagE[4];
__device__ unsigned g_flagD[4];

// ---------------- helpers ----------------
__device__ __forceinline__ unsigned long long dupf(float v){
    unsigned long long r; asm("mov.b64 %0, {%1,%1};" : "=l"(r) : "f"(v)); return r;
}
__device__ __forceinline__ float2 ull2f(unsigned long long v){
    float2 r; asm("mov.b64 {%0,%1}, %2;" : "=f"(r.x), "=f"(r.y) : "l"(v)); return r;
}
__device__ __forceinline__ void ffma2(unsigned long long& d, unsigned long long a, unsigned long long b){
    asm("fma.rn.f32x2 %0, %1, %2, %0;" : "+l"(d) : "l"(a), "l"(b));
}
__device__ __forceinline__ float sigf(float x){ return 1.f/(1.f + __expf(-x)); }
__device__ __forceinline__ float tanh_f(float x){ return 2.f/(1.f + __expf(-2.f*x)) - 1.f; }

__device__ __forceinline__ void cpa16s(uint32_t dst, const void* src){
    asm volatile("cp.async.cg.shared.global [%0], [%1], 16;" :: "r"(dst), "l"(src));
}
__device__ __forceinline__ void cpa_commit(){ asm volatile("cp.async.commit_group;" ::: "memory"); }
__device__ __forceinline__ void cpa_wait0(){ asm volatile("cp.async.wait_group 0;" ::: "memory"); }

__device__ __forceinline__ void ldsm4(uint32_t* r, uint32_t addr){
    asm volatile("ldmatrix.sync.aligned.m8n8.x4.shared.b16 {%0,%1,%2,%3}, [%4];"
        : "=r"(r[0]), "=r"(r[1]), "=r"(r[2]), "=r"(r[3]) : "r"(addr));
}
__device__ __forceinline__ void hmma(float* c, const uint32_t* a, const uint32_t* b){
    asm volatile("mma.sync.aligned.m16n8k16.row.col.f32.f16.f16.f32 "
        "{%0,%1,%2,%3}, {%4,%5,%6,%7}, {%8,%9}, {%0,%1,%2,%3};"
        : "+f"(c[0]), "+f"(c[1]), "+f"(c[2]), "+f"(c[3])
        : "r"(a[0]), "r"(a[1]), "r"(a[2]), "r"(a[3]), "r"(b[0]), "r"(b[1]));
}

__device__ __forceinline__ void spin_ge(unsigned* p, unsigned tgt){
    unsigned v;
    do {
        asm volatile("ld.acquire.gpu.u32 %0, [%1];" : "=r"(v) : "l"(p) : "memory");
    } while (v < tgt);
}
__device__ __forceinline__ void post_flag(unsigned* p){
    asm volatile("red.release.gpu.global.add.u32 [%0], %1;" :: "l"(p), "r"(1u) : "memory");
}

// ---------------- prep kernels ----------------
__global__ void k_bias(const float* __restrict__ ebi, const float* __restrict__ ebh,
                       const float* __restrict__ dbi, const float* __restrict__ dbh,
                       const float* __restrict__ dWih, const float* __restrict__ fcb){
    int n = blockIdx.x*blockDim.x + threadIdx.x;
    if (n < GG){
        g_bias_enc[n] = ebi[n] + ebh[n];
        float b = dbi[n] + dbh[n];
        const float* w = dWih + (size_t)n*DD;
        #pragma unroll 4
        for (int d = 0; d < DD; d++) b += fcb[d]*w[d];
        g_bcomb[n] = b;
    }
}

__global__ void k_wcomb(const float* __restrict__ dWih, const float* __restrict__ dWhh,
                        const float* __restrict__ fcW){
    __shared__ float sf[DD][64];
    __shared__ float sw[32][DD];
    int nt = blockIdx.x >> 3, kt = blockIdx.x & 7;
    int n0 = nt*32, k0 = kt*64;
    int tid = threadIdx.x;
    for (int idx = tid; idx < DD*64; idx += 256){
        int d = idx >> 6, kk = idx & 63;
        sf[d][kk] = fcW[(size_t)d*HH + k0 + kk];
    }
    for (int idx = tid; idx < 32*DD; idx += 256){
        int nn = idx / DD, d = idx % DD;
        sw[nn][d] = dWih[(size_t)(n0+nn)*DD + d];
    }
    __syncthreads();
    int nn = tid >> 3, kb = (tid & 7)*8;
    float a[8];
    #pragma unroll
    for (int i = 0; i < 8; i++) a[i] = dWhh[(size_t)(n0+nn)*HH + k0 + kb + i];
    for (int d = 0; d < DD; d++){
        float w = sw[nn][d];
        #pragma unroll
        for (int i = 0; i < 8; i++) a[i] += w * sf[d][kb+i];
    }
    #pragma unroll
    for (int i = 0; i < 8; i++) g_Wcomb[(size_t)(n0+nn)*HH + k0 + kb + i] = a[i];
}

__global__ void k_tx(const float* __restrict__ traj){
    if (blockIdx.x == 0 && threadIdx.x < 8){
        if (threadIdx.x < 4) g_flagE[threadIdx.x] = 0u;
        else                 g_flagD[threadIdx.x - 4] = 0u;
    }
    size_t N = (size_t)BB*TT*DD;
    for (size_t i = (size_t)blockIdx.x*blockDim.x + threadIdx.x; i < N; i += (size_t)gridDim.x*blockDim.x)
        g_txh[i] = __float2half_rn(traj[i]);
}

__global__ void k_x1(const float* __restrict__ fcW, const float* __restrict__ fcb){
    int b = blockIdx.x, tid = threadIdx.x;
    __shared__ float qs[HH];
    qs[tid]       = g_quant[(size_t)b*HH + tid];
    qs[tid + 256] = g_quant[(size_t)b*HH + tid + 256];
    __syncthreads();
    if (tid < DD){
        const float* w = fcW + (size_t)tid*HH;
        float s = fcb[tid];
        for (int k = 0; k < HH; k++) s += w[k]*qs[k];
        g_tmpT[tid*BB + b] = s;
    }
}

__global__ void k_corr(const float* __restrict__ dWih){
    int n = blockIdx.x, b = threadIdx.x;
    __shared__ float wd[DD];
    if (b < DD) wd[b] = dWih[(size_t)n*DD + b];
    __syncthreads();
    float s = 0.f;
    #pragma unroll 4
    for (int d = 0; d < DD; d++) s += wd[d] * g_tmpT[d*BB + b];
    g_corr[(size_t)b*GG + n] = s;
}

__global__ void k_decprep(){
    int i = blockIdx.x*blockDim.x + threadIdx.x;
    if (i < BB*HH) g_h16[0][i] = __float2half_rn(g_quant[i]);
}

// ---------------- persistent recurrent kernel ----------------
// Block: 64 rows x 64 gate-cols. 8 warps = 2M(32 rows) x 2N(32 cols) x 2K.
// h-path: 2-term fp16 split W (hi+lo). Enc x-path: 1-term (x fp16, W_x hi).
// K-split partials reduced via smem (aliases h-stage region); single flag/step.
template<bool ENC>
__global__ void __launch_bounds__(256, 1) k_rnn(const float* __restrict__ eWih,
                                                const float* __restrict__ eWhh){
    extern __shared__ __half smh[];
    constexpr int SW = 520;                               // W_hh smem stride (halves)
    constexpr uint32_t WHALF = 64u*SW*2u;                 // 66560 B (hi->lo)
    constexpr uint32_t WXO = ENC ? 2u*WHALF : 0u;         // enc W_x region (133120)
    constexpr uint32_t XO  = ENC ? (WXO + 11264u) : 0u;   // enc x tile (144384)
    constexpr uint32_t HSO = ENC ? (XO + 11264u) : 2u*WHALF; // h: 4 x 17408

    const int tid = threadIdx.x;
    const int wid = tid >> 5, lane = tid & 31;
    const int wm = wid & 1, wn = (wid >> 1) & 1, kh = wid >> 2;
    const int rg = blockIdx.x >> 5, cg = blockIdx.x & 31;
    const int row0 = rg*64, j0 = cg*16;
    const uint32_t smb = (uint32_t)__cvta_generic_to_shared(smh);
    unsigned* flg = (ENC ? g_flagE : g_flagD) + rg;

    // ---- W fill: W_hh (or Wcomb) hi+lo ----
    for (int idx = tid; idx < 64*512; idx += 256){
        int br = idx >> 9, k = idx & 511;
        int n = ((br >> 3) & 3)*HH + j0 + (br >> 5)*8 + (br & 7);
        float v = ENC ? eWhh[(size_t)n*HH + k] : g_Wcomb[(size_t)n*HH + k];
        __half h = __float2half_rn(v);
        smh[br*SW + k] = h;
        smh[64*SW + br*SW + k] = __float2half_rn(v - __half2float(h));
    }
    // ---- enc: W_x hi (1-term), [64][88] ----
    if (ENC){
        for (int idx = tid; idx < 64*DD; idx += 256){
            int br = idx / DD, k = idx - br*DD;
            int n = ((br >> 3) & 3)*HH + j0 + (br >> 5)*8 + (br & 7);
            smh[WXO/2 + br*88 + k] = __float2half_rn(eWih[(size_t)n*DD + k]);
        }
    }

    const int j0w = j0 + wn*8;
    const int ecol = (lane & 3)*2;
    float bias[4][2];
    if (kh == 0){
        #pragma unroll
        for (int g = 0; g < 4; g++)
            #pragma unroll
            for (int e = 0; e < 2; e++)
                bias[g][e] = (ENC ? g_bias_enc : g_bcomb)[g*HH + j0w + ecol + e];
    }
    float cst[2][2][2] = {{{0.f,0.f},{0.f,0.f}},{{0.f,0.f},{0.f,0.f}}};

    // lane address components
    const uint32_t aoff  = (uint32_t)((lane & 15)*272 + (lane >> 4)*16);  // h tile (stride 272B)
    const uint32_t aoffx = (uint32_t)((lane & 15)*176 + (lane >> 4)*16);  // x tile (stride 176B)
    const uint32_t bB0 = smb + (uint32_t)(((lane & 7) + ((lane >> 4) & 1)*8 + wn*32)*SW)*2u
                             + (uint32_t)(((lane >> 3) & 1)*16);
    const uint32_t bBx = smb + WXO + (uint32_t)(((lane & 7) + ((lane >> 4) & 1)*8 + wn*32)*176)
                             + (uint32_t)(((lane >> 3) & 1)*16);
    float* red = reinterpret_cast<float*>(reinterpret_cast<char*>(smh) + HSO); // aliases h region

    __syncthreads();

    for (int t = 0; t < TT; t++){
        // ---- stage x (enc; no cross-block dep): 64 rows x 160B ----
        if (ENC){
            #pragma unroll
            for (int i = 0; i < 3; i++){
                int u = tid + i*256;
                if (u < 640){
                    int r = u/10, s = u - r*10;
                    cpa16s(smb + XO + (uint32_t)(r*176 + s*16),
                           g_txh + ((size_t)(row0+r)*TT + t)*DD + s*8);
                }
            }
        }
        // ---- wait producers, stage h (64 rows x 1KB) ----
        if (t > 0){
            if (tid == 0) spin_ge(flg, 32u*(unsigned)t);
            __syncthreads();
        }
        const bool haveH = (!ENC) || (t > 0);
        if (haveH){
            const __half* src = g_h16[t & 1];
            #pragma unroll
            for (int i = 0; i < 16; i++){
                int u = tid + i*256;
                int c = u >> 10, r = (u >> 4) & 63, s = u & 15;
                cpa16s(smb + HSO + (uint32_t)(c*17408 + r*272 + s*16),
                       src + (size_t)(row0+r)*HH + c*128 + s*8);
            }
        }
        cpa_commit();
        cpa_wait0();
        __syncthreads();

        // ---- MMA ----
        float acc[2][4][4];
        #pragma unroll
        for (int p = 0; p < 2; p++)
            #pragma unroll
            for (int g = 0; g < 4; g++)
                #pragma unroll
                for (int i = 0; i < 4; i++) acc[p][g][i] = 0.f;

        if (haveH){
            #pragma unroll
            for (int cc = 0; cc < 2; cc++){
                int c = kh*2 + cc;
                uint32_t A0 = smb + HSO + (uint32_t)(c*17408 + (wm*32)*272) + aoff;
                uint32_t A1 = A0 + 16*272;
                #pragma unroll
                for (int k8 = 0; k8 < 8; k8++){
                    uint32_t a0[4], a1[4], b0h[4], b1h[4], b0l[4], b1l[4];
                    ldsm4(a0, A0 + k8*32);
                    ldsm4(a1, A1 + k8*32);
                    uint32_t bk = bB0 + (uint32_t)((c*8 + k8)*32);
                    ldsm4(b0h, bk);
                    ldsm4(b1h, bk + 16*SW*2);
                    ldsm4(b0l, bk + WHALF);
                    ldsm4(b1l, bk + WHALF + 16*SW*2);
                    hmma(acc[0][0], a0, b0h); hmma(acc[0][1], a0, b0h+2);
                    hmma(acc[0][2], a0, b1h); hmma(acc[0][3], a0, b1h+2);
                    hmma(acc[1][0], a1, b0h); hmma(acc[1][1], a1, b0h+2);
                    hmma(acc[1][2], a1, b1h); hmma(acc[1][3], a1, b1h+2);
                    hmma(acc[0][0], a0, b0l); hmma(acc[0][1], a0, b0l+2);
                    hmma(acc[0][2], a0, b1l); hmma(acc[0][3], a0, b1l+2);
                    hmma(acc[1][0], a1, b0l); hmma(acc[1][1], a1, b0l+2);
                    hmma(acc[1][2], a1, b1l); hmma(acc[1][3], a1, b1l+2);
                }
            }
        }
        if (ENC && kh == 0){
            uint32_t A0 = smb + XO + (uint32_t)((wm*32)*176) + aoffx;
            uint32_t A1 = A0 + 16*176;
            #pragma unroll
            for (int xk = 0; xk < 5; xk++){
                uint32_t a0[4], a1[4], b0h[4], b1h[4];
                ldsm4(a0, A0 + xk*32);
                ldsm4(a1, A1 + xk*32);
                uint32_t bk = bBx + (uint32_t)(xk*32);
                ldsm4(b0h, bk);
                ldsm4(b1h, bk + 16*176);
                hmma(acc[0][0], a0, b0h); hmma(acc[0][1], a0, b0h+2);
                hmma(acc[0][2], a0, b1h); hmma(acc[0][3], a0, b1h+2);
                hmma(acc[1][0], a1, b0h); hmma(acc[1][1], a1, b0h+2);
                hmma(acc[1][2], a1, b1h); hmma(acc[1][3], a1, b1h+2);
            }
        }

        // ---- K-split reduction (red aliases h region; all reads done first) ----
        __syncthreads();
        if (kh == 1){
            int rb = (wid - 4)*1024 + lane;
            #pragma unroll
            for (int p = 0; p < 2; p++)
                #pragma unroll
                for (int g = 0; g < 4; g++)
                    #pragma unroll
                    for (int i = 0; i < 4; i++)
                        red[rb + ((p*4 + g)*4 + i)*32] = acc[p][g][i];
        }
        __syncthreads();

        if (kh == 0){
            int rb = wid*1024 + lane;
            #pragma unroll
            for (int p = 0; p < 2; p++)
                #pragma unroll
                for (int g = 0; g < 4; g++)
                    #pragma unroll
                    for (int i = 0; i < 4; i++)
                        acc[p][g][i] += red[rb + ((p*4 + g)*4 + i)*32];

            const int nimg = (t+1) & 1;
            #pragma unroll
            for (int p = 0; p < 2; p++){
                #pragma unroll
                for (int h8 = 0; h8 < 2; h8++){
                    int r = row0 + wm*32 + p*16 + (lane >> 2) + h8*8;
                    float hv[2];
                    #pragma unroll
                    for (int e = 0; e < 2; e++){
                        float gi = acc[p][0][h8*2+e] + bias[0][e];
                        float gf = acc[p][1][h8*2+e] + bias[1][e];
                        float gg = acc[p][2][h8*2+e] + bias[2][e];
                        float go = acc[p][3][h8*2+e] + bias[3][e];
                        if (!ENC && t == 0){
                            const float* cp = &g_corr[(size_t)r*GG + j0w + ecol + e];
                            gi -= cp[0]; gf -= cp[HH]; gg -= cp[2*HH]; go -= cp[3*HH];
                        }
                        float cn = sigf(gf)*cst[p][h8][e] + sigf(gi)*tanh_f(gg);
                        cst[p][h8][e] = cn;
                        hv[e] = sigf(go)*tanh_f(cn);
                    }
                    __half h0 = __float2half_rn(hv[0]);
                    __half h1 = __float2half_rn(hv[1]);
                    uint32_t uh = (uint32_t)__half_as_ushort(h0) | ((uint32_t)__half_as_ushort(h1) << 16);
                    *(uint32_t*)&g_h16[nimg][(size_t)r*HH + j0w + ecol] = uh;
                    if (ENC){
                        if (t == TT-1){
                            g_hA[(size_t)r*HH + j0w + ecol]     = hv[0];
                            g_hA[(size_t)r*HH + j0w + ecol + 1] = hv[1];
                        }
                    } else {
                        float2 f2; f2.x = hv[0]; f2.y = hv[1];
                        *(float2*)&g_Hbuf[((size_t)t*BB + r)*HH + j0w + ecol] = f2;
                    }
                }
            }
        }
        __syncthreads();
        if (tid == 0) post_flag(flg);
    }
}

// ---------------- VQ ----------------
__global__ void k_vq(const float* __restrict__ emb){
    int b = blockIdx.x, tid = threadIdx.x;
    __shared__ float zs[HH];
    __shared__ float rs[256];
    __shared__ int   rk[256];
    zs[tid]       = g_hA[(size_t)b*HH + tid];
    zs[tid + 256] = g_hA[(size_t)b*HH + tid + 256];
    __syncthreads();
    float bestS = 3.4e38f; int bestK = 0;
    #pragma unroll
    for (int kq = 0; kq < 2; kq++){
        int k = tid + kq*256;
        const float* e = emb + (size_t)k*HH;
        float s = 0.f, dt = 0.f;
        for (int jj = 0; jj < HH; jj++){ float ev = e[jj]; s += ev*ev; dt += ev*zs[jj]; }
        float score = s - 2.f*dt;
        if (score < bestS || (score == bestS && k < bestK)){ bestS = score; bestK = k; }
    }
    rs[tid] = bestS; rk[tid] = bestK;
    __syncthreads();
    for (int s = 128; s > 0; s >>= 1){
        if (tid < s){
            if (rs[tid+s] < rs[tid] || (rs[tid+s] == rs[tid] && rk[tid+s] < rk[tid])){
                rs[tid] = rs[tid+s]; rk[tid] = rk[tid+s];
            }
        }
        __syncthreads();
    }
    int idx = rk[0];
    if (tid == 0) g_idx[b] = idx;
    float lp = 0.f;
    #pragma unroll
    for (int kq = 0; kq < 2; kq++){
        int jj = tid + kq*256;
        float q = emb[(size_t)idx*HH + jj];
        g_quant[(size_t)b*HH + jj] = q;
        float dz = q - zs[jj];
        lp += dz*dz;
    }
    __syncthreads();
    rs[tid] = lp;
    __syncthreads();
    for (int s = 128; s > 0; s >>= 1){
        if (tid < s) rs[tid] += rs[tid+s];
        __syncthreads();
    }
    if (tid == 0) g_lossp[b] = rs[0];
}

__global__ void k_vqfinish(float* __restrict__ out){
    const size_t OFF = (size_t)BB*TT*DD;
    int tid = threadIdx.x;
    if (tid == 0){
        float tot = 0.f;
        for (int i = 0; i < BB; i++) tot += g_lossp[i];
        out[OFF] = 1.25f * tot / (float)(BB*HH);
    }
    out[OFF + 1 + tid] = (float)g_idx[tid];
}

// ---------------- recon head ----------------
__device__ __forceinline__ void stage_h32r(float hsb[32][68], const float* __restrict__ src, int stride){
    int kk = threadIdx.x & 31, rb = threadIdx.x >> 5;
    #pragma unroll
    for (int i = 0; i < 8; i++)
        hsb[kk][rb + i*8] = src[(size_t)(rb + i*8)*stride + kk];
}

__global__ void __launch_bounds__(256) k_recon(const float* __restrict__ fcW,
                                               const float* __restrict__ fcb,
                                               float* __restrict__ out){
    __shared__ __align__(16) float hsb[32][68];
    __shared__ unsigned long long wsd[32][DD];
    int t = blockIdx.x;
    int b0 = blockIdx.y * 64;
    int tid = threadIdx.x;
    int txd = tid & 15, tyb = tid >> 4;

    unsigned long long acc[5][2];
    #pragma unroll
    for (int s = 0; s < 5; s++){ acc[s][0] = 0ull; acc[s][1] = 0ull; }

    for (int c = 0; c < 16; c++){
        __syncthreads();
        stage_h32r(hsb, g_Hbuf + ((size_t)t*BB + b0)*HH + c*32, HH);
        {
            int kk = tid & 31, db = tid >> 5;
            #pragma unroll
            for (int i = 0; i < 10; i++){
                int d = db + i*8;
                wsd[kk][d] = dupf(fcW[(size_t)d*HH + c*32 + kk]);
            }
        }
        __syncthreads();
        #pragma unroll
        for (int kk = 0; kk < 32; kk++){
            ulonglong2 hp = *(const ulonglong2*)&hsb[kk][tyb*4];
            #pragma unroll
            for (int s = 0; s < 5; s++){
                unsigned long long w = wsd[kk][txd + 16*s];
                ffma2(acc[s][0], hp.x, w);
                ffma2(acc[s][1], hp.y, w);
            }
        }
    }
    #pragma unroll
    for (int s = 0; s < 5; s++){
        int d = txd + 16*s;
        float bv = fcb[d];
        #pragma unroll
        for (int p = 0; p < 2; p++){
            float2 v = ull2f(acc[s][p]);
            int b = b0 + tyb*4 + p*2;
            out[((size_t)b*TT + t)*DD + d]     = v.x + bv;
            out[((size_t)(b+1)*TT + t)*DD + d] = v.y + bv;
        }
    }
}

// ---------------- launcher ----------------
extern "C" void kernel_launch(void* const* d_in, const int* in_sizes, int n_in,
                              void* d_out, int out_size){
    (void)in_sizes; (void)n_in; (void)out_size;
    const float* traj = (const float*)d_in[0];
    const float* eWih = (const float*)d_in[2];
    const float* eWhh = (const float*)d_in[3];
    const float* ebi  = (const float*)d_in[4];
    const float* ebh  = (const float*)d_in[5];
    const float* emb  = (const float*)d_in[6];
    const float* dWih = (const float*)d_in[7];
    const float* dWhh = (const float*)d_in[8];
    const float* dbi  = (const float*)d_in[9];
    const float* dbh  = (const float*)d_in[10];
    const float* fcW  = (const float*)d_in[11];
    const float* fcb  = (const float*)d_in[12];
    float* out = (float*)d_out;

    const int SME = 133120 + 11264 + 11264 + 4*17408;  // 225280 B
    const int SMD = 133120 + 4*17408;                  // 202752 B
    cudaFuncSetAttribute(k_rnn<true>,  cudaFuncAttributeMaxDynamicSharedMemorySize, SME);
    cudaFuncSetAttribute(k_rnn<false>, cudaFuncAttributeMaxDynamicSharedMemorySize, SMD);

    k_bias<<<8, 256>>>(ebi, ebh, dbi, dbh, dWih, fcb);
    k_wcomb<<<512, 256>>>(dWih, dWhh, fcW);
    k_tx<<<1024, 256>>>(traj);
    k_rnn<true><<<NBLK, 256, SME>>>(eWih, eWhh);   // launch #4 -> ncu capture slot
    k_vq<<<BB, 256>>>(emb);
    k_vqfinish<<<1, 256>>>(out);
    k_x1<<<BB, 256>>>(fcW, fcb);
    k_corr<<<GG, 256>>>(dWih);
    k_decprep<<<512, 256>>>();
    k_rnn<false><<<NBLK, 256, SMD>>>(eWih, eWhh);
    k_recon<<<dim3(TT, 4), 256>>>(fcW, fcb, out);
}

// round 10
// speedup vs baseline: 1.0501x; 1.0252x over previous
#include <cuda_runtime.h>
#include <cuda_fp16.h>
#include <cstdint>

#define BB 256
#define TT 256
#define DD 80
#define HH 512
#define GG 2048
#define NBLK 128

// ---------------- device scratch ----------------
__device__ __align__(16) __half g_h16[2][(size_t)BB*HH]; // [parity]
__device__ __align__(16) __half g_txh[(size_t)BB*TT*DD];
__device__ float g_Wcomb[(size_t)GG*HH];
__device__ float g_bias_enc[GG];
__device__ float g_bcomb[GG];
__device__ float g_quant[BB*HH];
__device__ float g_hA[BB*HH];
__device__ float g_tmpT[DD*BB];
__device__ float g_corr[(size_t)BB*GG];
__device__ float g_lossp[BB];
__device__ int   g_idx[BB];
__device__ float g_Hbuf[(size_t)TT*BB*HH];
__device__ unsigned g_flagE[4];
__device__ unsigned g_flagD[4];

// ---------------- helpers ----------------
__device__ __forceinline__ unsigned long long dupf(float v){
    unsigned long long r; asm("mov.b64 %0, {%1,%1};" : "=l"(r) : "f"(v)); return r;
}
__device__ __forceinline__ float2 ull2f(unsigned long long v){
    float2 r; asm("mov.b64 {%0,%1}, %2;" : "=f"(r.x), "=f"(r.y) : "l"(v)); return r;
}
__device__ __forceinline__ void ffma2(unsigned long long& d, unsigned long long a, unsigned long long b){
    asm("fma.rn.f32x2 %0, %1, %2, %0;" : "+l"(d) : "l"(a), "l"(b));
}
__device__ __forceinline__ float sigf(float x){ return 1.f/(1.f + __expf(-x)); }
__device__ __forceinline__ float tanh_f(float x){ return 2.f/(1.f + __expf(-2.f*x)) - 1.f; }

__device__ __forceinline__ void cpa16s(uint32_t dst, const void* src){
    asm volatile("cp.async.cg.shared.global [%0], [%1], 16;" :: "r"(dst), "l"(src));
}
__device__ __forceinline__ void cpa_commit(){ asm volatile("cp.async.commit_group;" ::: "memory"); }
__device__ __forceinline__ void cpa_wait0(){ asm volatile("cp.async.wait_group 0;" ::: "memory"); }
__device__ __forceinline__ void cpa_wait1(){ asm volatile("cp.async.wait_group 1;" ::: "memory"); }

__device__ __forceinline__ void ldsm4(uint32_t* r, uint32_t addr){
    asm volatile("ldmatrix.sync.aligned.m8n8.x4.shared.b16 {%0,%1,%2,%3}, [%4];"
        : "=r"(r[0]), "=r"(r[1]), "=r"(r[2]), "=r"(r[3]) : "r"(addr));
}
__device__ __forceinline__ void hmma(float* c, const uint32_t* a, const uint32_t* b){
    asm volatile("mma.sync.aligned.m16n8k16.row.col.f32.f16.f16.f32 "
        "{%0,%1,%2,%3}, {%4,%5,%6,%7}, {%8,%9}, {%0,%1,%2,%3};"
        : "+f"(c[0]), "+f"(c[1]), "+f"(c[2]), "+f"(c[3])
        : "r"(a[0]), "r"(a[1]), "r"(a[2]), "r"(a[3]), "r"(b[0]), "r"(b[1]));
}

__device__ __forceinline__ void spin_ge(unsigned* p, unsigned tgt){
    unsigned v;
    do {
        asm volatile("ld.acquire.gpu.u32 %0, [%1];" : "=r"(v) : "l"(p) : "memory");
    } while (v < tgt);
}
__device__ __forceinline__ void post_flag(unsigned* p){
    asm volatile("red.release.gpu.global.add.u32 [%0], %1;" :: "l"(p), "r"(1u) : "memory");
}

// ---------------- prep kernels ----------------
__global__ void k_bias(const float* __restrict__ ebi, const float* __restrict__ ebh,
                       const float* __restrict__ dbi, const float* __restrict__ dbh,
                       const float* __restrict__ dWih, const float* __restrict__ fcb){
    int n = blockIdx.x*blockDim.x + threadIdx.x;
    if (n < GG){
        g_bias_enc[n] = ebi[n] + ebh[n];
        float b = dbi[n] + dbh[n];
        const float* w = dWih + (size_t)n*DD;
        #pragma unroll 4
        for (int d = 0; d < DD; d++) b += fcb[d]*w[d];
        g_bcomb[n] = b;
    }
}

__global__ void k_wcomb(const float* __restrict__ dWih, const float* __restrict__ dWhh,
                        const float* __restrict__ fcW){
    __shared__ float sf[DD][64];
    __shared__ float sw[32][DD];
    int nt = blockIdx.x >> 3, kt = blockIdx.x & 7;
    int n0 = nt*32, k0 = kt*64;
    int tid = threadIdx.x;
    for (int idx = tid; idx < DD*64; idx += 256){
        int d = idx >> 6, kk = idx & 63;
        sf[d][kk] = fcW[(size_t)d*HH + k0 + kk];
    }
    for (int idx = tid; idx < 32*DD; idx += 256){
        int nn = idx / DD, d = idx % DD;
        sw[nn][d] = dWih[(size_t)(n0+nn)*DD + d];
    }
    __syncthreads();
    int nn = tid >> 3, kb = (tid & 7)*8;
    float a[8];
    #pragma unroll
    for (int i = 0; i < 8; i++) a[i] = dWhh[(size_t)(n0+nn)*HH + k0 + kb + i];
    for (int d = 0; d < DD; d++){
        float w = sw[nn][d];
        #pragma unroll
        for (int i = 0; i < 8; i++) a[i] += w * sf[d][kb+i];
    }
    #pragma unroll
    for (int i = 0; i < 8; i++) g_Wcomb[(size_t)(n0+nn)*HH + k0 + kb + i] = a[i];
}

__global__ void k_tx(const float* __restrict__ traj){
    if (blockIdx.x == 0 && threadIdx.x < 8){
        if (threadIdx.x < 4) g_flagE[threadIdx.x] = 0u;
        else                 g_flagD[threadIdx.x - 4] = 0u;
    }
    size_t N = (size_t)BB*TT*DD;
    for (size_t i = (size_t)blockIdx.x*blockDim.x + threadIdx.x; i < N; i += (size_t)gridDim.x*blockDim.x)
        g_txh[i] = __float2half_rn(traj[i]);
}

__global__ void k_x1(const float* __restrict__ fcW, const float* __restrict__ fcb){
    int b = blockIdx.x, tid = threadIdx.x;
    __shared__ float qs[HH];
    qs[tid]       = g_quant[(size_t)b*HH + tid];
    qs[tid + 256] = g_quant[(size_t)b*HH + tid + 256];
    __syncthreads();
    if (tid < DD){
        const float* w = fcW + (size_t)tid*HH;
        float s = fcb[tid];
        for (int k = 0; k < HH; k++) s += w[k]*qs[k];
        g_tmpT[tid*BB + b] = s;
    }
}

__global__ void k_corr(const float* __restrict__ dWih){
    int n = blockIdx.x, b = threadIdx.x;
    __shared__ float wd[DD];
    if (b < DD) wd[b] = dWih[(size_t)n*DD + b];
    __syncthreads();
    float s = 0.f;
    #pragma unroll 4
    for (int d = 0; d < DD; d++) s += wd[d] * g_tmpT[d*BB + b];
    g_corr[(size_t)b*GG + n] = s;
}

__global__ void k_decprep(){
    int i = blockIdx.x*blockDim.x + threadIdx.x;
    if (i < BB*HH) g_h16[0][i] = __float2half_rn(g_quant[i]);
}

// ---------------- persistent recurrent kernel ----------------
// Block: 64 rows x 64 gate-cols. 8 warps = 2M x 2N x 2K.
// Enc h-path: 2-term fp16 split W (hi+lo); enc x-path 1-term.
// Dec: 1-term (Wcomb hi only) -- halves decoder HMMA.
// Two-phase cp.async staging (chunks {0,2} then {1,3}) overlapped with MMA.
// Epilogue split by row-half: warp kh owns p=kh.
template<bool ENC>
__global__ void __launch_bounds__(256, 1) k_rnn(const float* __restrict__ eWih,
                                                const float* __restrict__ eWhh){
    extern __shared__ __half smh[];
    constexpr int SW = 520;
    constexpr uint32_t WHALF = 64u*SW*2u;                 // 66560 B
    constexpr uint32_t WB  = ENC ? 2u*WHALF : WHALF;      // W_hh region
    constexpr uint32_t WXO = WB;                          // enc W_x
    constexpr uint32_t XO  = ENC ? (WXO + 11264u) : 0u;   // enc x tile
    constexpr uint32_t HSO = ENC ? (XO + 11264u) : WB;    // h: 4 x 17408

    const int tid = threadIdx.x;
    const int wid = tid >> 5, lane = tid & 31;
    const int wm = wid & 1, wn = (wid >> 1) & 1, kh = wid >> 2;
    const int rg = blockIdx.x >> 5, cg = blockIdx.x & 31;
    const int row0 = rg*64, j0 = cg*16;
    const uint32_t smb = (uint32_t)__cvta_generic_to_shared(smh);
    unsigned* flg = (ENC ? g_flagE : g_flagD) + rg;

    // ---- W fill ----
    for (int idx = tid; idx < 64*512; idx += 256){
        int br = idx >> 9, k = idx & 511;
        int n = ((br >> 3) & 3)*HH + j0 + (br >> 5)*8 + (br & 7);
        float v = ENC ? eWhh[(size_t)n*HH + k] : g_Wcomb[(size_t)n*HH + k];
        __half h = __float2half_rn(v);
        smh[br*SW + k] = h;
        if (ENC) smh[64*SW + br*SW + k] = __float2half_rn(v - __half2float(h));
    }
    if (ENC){
        for (int idx = tid; idx < 64*DD; idx += 256){
            int br = idx / DD, k = idx - br*DD;
            int n = ((br >> 3) & 3)*HH + j0 + (br >> 5)*8 + (br & 7);
            smh[WXO/2 + br*88 + k] = __float2half_rn(eWih[(size_t)n*DD + k]);
        }
    }

    const int j0w = j0 + wn*8;
    const int ecol = (lane & 3)*2;
    float bias[4][2];
    #pragma unroll
    for (int g = 0; g < 4; g++)
        #pragma unroll
        for (int e = 0; e < 2; e++)
            bias[g][e] = (ENC ? g_bias_enc : g_bcomb)[g*HH + j0w + ecol + e];
    float cst[2][2] = {{0.f,0.f},{0.f,0.f}};   // own row-half only (p = kh)

    const uint32_t aoff  = (uint32_t)((lane & 15)*272 + (lane >> 4)*16);
    const uint32_t aoffx = (uint32_t)((lane & 15)*176 + (lane >> 4)*16);
    const uint32_t bB0 = smb + (uint32_t)(((lane & 7) + ((lane >> 4) & 1)*8 + wn*32)*SW)*2u
                             + (uint32_t)(((lane >> 3) & 1)*16);
    const uint32_t bBx = smb + WXO + (uint32_t)(((lane & 7) + ((lane >> 4) & 1)*8 + wn*32)*176)
                             + (uint32_t)(((lane >> 3) & 1)*16);
    float* red = reinterpret_cast<float*>(reinterpret_cast<char*>(smh) + HSO); // aliases h region
    const int pairId = wm*2 + wn;

    __syncthreads();

    for (int t = 0; t < TT; t++){
        const bool haveH = (!ENC) || (t > 0);

        // ---- wait producers ----
        if (t > 0){
            if (tid == 0) spin_ge(flg, 32u*(unsigned)t);
            __syncthreads();
        }

        // ---- stage group A: x (enc) + h chunks {0,2} ----
        if (ENC){
            #pragma unroll
            for (int i = 0; i < 3; i++){
                int u = tid + i*256;
                if (u < 640){
                    int r = u/10, s = u - r*10;
                    cpa16s(smb + XO + (uint32_t)(r*176 + s*16),
                           g_txh + ((size_t)(row0+r)*TT + t)*DD + s*8);
                }
            }
        }
        const __half* hsrc = g_h16[t & 1];
        if (haveH){
            #pragma unroll
            for (int i = 0; i < 8; i++){
                int u = tid + ((i < 4) ? i : i + 4)*256;       // chunks 0, 2
                int c = u >> 10, r = (u >> 4) & 63, s = u & 15;
                cpa16s(smb + HSO + (uint32_t)(c*17408 + r*272 + s*16),
                       hsrc + (size_t)(row0+r)*HH + c*128 + s*8);
            }
        }
        cpa_commit();
        // ---- stage group B: h chunks {1,3} ----
        if (haveH){
            #pragma unroll
            for (int i = 0; i < 8; i++){
                int u = tid + ((i < 4) ? i + 4 : i + 8)*256;   // chunks 1, 3
                int c = u >> 10, r = (u >> 4) & 63, s = u & 15;
                cpa16s(smb + HSO + (uint32_t)(c*17408 + r*272 + s*16),
                       hsrc + (size_t)(row0+r)*HH + c*128 + s*8);
            }
        }
        cpa_commit();

        float acc[2][4][4];
        #pragma unroll
        for (int p = 0; p < 2; p++)
            #pragma unroll
            for (int g = 0; g < 4; g++)
                #pragma unroll
                for (int i = 0; i < 4; i++) acc[p][g][i] = 0.f;

        // ---- MMA on one h chunk ----
        auto mma_h = [&](int c){
            uint32_t A0 = smb + HSO + (uint32_t)(c*17408 + (wm*32)*272) + aoff;
            uint32_t A1 = A0 + 16*272;
            #pragma unroll
            for (int k8 = 0; k8 < 8; k8++){
                uint32_t a0[4], a1[4], b0h[4], b1h[4];
                ldsm4(a0, A0 + k8*32);
                ldsm4(a1, A1 + k8*32);
                uint32_t bk = bB0 + (uint32_t)((c*8 + k8)*32);
                ldsm4(b0h, bk);
                ldsm4(b1h, bk + 16*SW*2);
                hmma(acc[0][0], a0, b0h); hmma(acc[0][1], a0, b0h+2);
                hmma(acc[0][2], a0, b1h); hmma(acc[0][3], a0, b1h+2);
                hmma(acc[1][0], a1, b0h); hmma(acc[1][1], a1, b0h+2);
                hmma(acc[1][2], a1, b1h); hmma(acc[1][3], a1, b1h+2);
                if (ENC){
                    uint32_t b0l[4], b1l[4];
                    ldsm4(b0l, bk + WHALF);
                    ldsm4(b1l, bk + WHALF + 16*SW*2);
                    hmma(acc[0][0], a0, b0l); hmma(acc[0][1], a0, b0l+2);
                    hmma(acc[0][2], a0, b1l); hmma(acc[0][3], a0, b1l+2);
                    hmma(acc[1][0], a1, b0l); hmma(acc[1][1], a1, b0l+2);
                    hmma(acc[1][2], a1, b1l); hmma(acc[1][3], a1, b1l+2);
                }
            }
        };
        auto mma_x = [&](int xk){
            uint32_t A0 = smb + XO + (uint32_t)((wm*32)*176) + aoffx;
            uint32_t A1 = A0 + 16*176;
            uint32_t a0[4], a1[4], b0h[4], b1h[4];
            ldsm4(a0, A0 + xk*32);
            ldsm4(a1, A1 + xk*32);
            uint32_t bk = bBx + (uint32_t)(xk*32);
            ldsm4(b0h, bk);
            ldsm4(b1h, bk + 16*176);
            hmma(acc[0][0], a0, b0h); hmma(acc[0][1], a0, b0h+2);
            hmma(acc[0][2], a0, b1h); hmma(acc[0][3], a0, b1h+2);
            hmma(acc[1][0], a1, b0h); hmma(acc[1][1], a1, b0h+2);
            hmma(acc[1][2], a1, b1h); hmma(acc[1][3], a1, b1h+2);
        };

        // phase 0: group A ready (chunks 0,2 + x)
        cpa_wait1();
        __syncthreads();
        if (haveH) mma_h(kh*2);
        if (ENC){
            if (kh == 0){ mma_x(0); mma_x(1); mma_x(2); }
            else        { mma_x(3); mma_x(4); }
        }
        // phase 1: group B ready (chunks 1,3)
        cpa_wait0();
        __syncthreads();
        if (haveH) mma_h(kh*2 + 1);

        // ---- cross-K exchange of the non-owned row-half ----
        __syncthreads();   // all ldsm reads of h region done (red aliases it)
        {
            const int other = 1 - kh;
            #pragma unroll
            for (int g = 0; g < 4; g++)
                *(float4*)&red[(((g*8 + pairId*2 + other)*32) + lane)*4] =
                    make_float4(acc[other][g][0], acc[other][g][1], acc[other][g][2], acc[other][g][3]);
        }
        __syncthreads();
        {
            #pragma unroll
            for (int g = 0; g < 4; g++){
                float4 v = *(const float4*)&red[(((g*8 + pairId*2 + kh)*32) + lane)*4];
                acc[kh][g][0] += v.x; acc[kh][g][1] += v.y;
                acc[kh][g][2] += v.z; acc[kh][g][3] += v.w;
            }
        }

        // ---- epilogue: this warp owns row-half p = kh ----
        const int nimg = (t+1) & 1;
        float hvs[2][2];
        #pragma unroll
        for (int h8 = 0; h8 < 2; h8++){
            int r = row0 + wm*32 + kh*16 + (lane >> 2) + h8*8;
            #pragma unroll
            for (int e = 0; e < 2; e++){
                float gi = acc[kh][0][h8*2+e] + bias[0][e];
                float gf = acc[kh][1][h8*2+e] + bias[1][e];
                float gg = acc[kh][2][h8*2+e] + bias[2][e];
                float go = acc[kh][3][h8*2+e] + bias[3][e];
                if (!ENC && t == 0){
                    const float* cp = &g_corr[(size_t)r*GG + j0w + ecol + e];
                    gi -= cp[0]; gf -= cp[HH]; gg -= cp[2*HH]; go -= cp[3*HH];
                }
                float cn = sigf(gf)*cst[h8][e] + sigf(gi)*tanh_f(gg);
                cst[h8][e] = cn;
                hvs[h8][e] = sigf(go)*tanh_f(cn);
            }
            __half h0 = __float2half_rn(hvs[h8][0]);
            __half h1 = __float2half_rn(hvs[h8][1]);
            uint32_t uh = (uint32_t)__half_as_ushort(h0) | ((uint32_t)__half_as_ushort(h1) << 16);
            *(uint32_t*)&g_h16[nimg][(size_t)r*HH + j0w + ecol] = uh;
        }
        __syncthreads();
        if (tid == 0) post_flag(flg);

        // secondary outputs after the flag (off the inter-block critical path)
        #pragma unroll
        for (int h8 = 0; h8 < 2; h8++){
            int r = row0 + wm*32 + kh*16 + (lane >> 2) + h8*8;
            if (ENC){
                if (t == TT-1){
                    g_hA[(size_t)r*HH + j0w + ecol]     = hvs[h8][0];
                    g_hA[(size_t)r*HH + j0w + ecol + 1] = hvs[h8][1];
                }
            } else {
                float2 f2; f2.x = hvs[h8][0]; f2.y = hvs[h8][1];
                *(float2*)&g_Hbuf[((size_t)t*BB + r)*HH + j0w + ecol] = f2;
            }
        }
    }
}

// ---------------- VQ ----------------
__global__ void k_vq(const float* __restrict__ emb){
    int b = blockIdx.x, tid = threadIdx.x;
    __shared__ float zs[HH];
    __shared__ float rs[256];
    __shared__ int   rk[256];
    zs[tid]       = g_hA[(size_t)b*HH + tid];
    zs[tid + 256] = g_hA[(size_t)b*HH + tid + 256];
    __syncthreads();
    float bestS = 3.4e38f; int bestK = 0;
    #pragma unroll
    for (int kq = 0; kq < 2; kq++){
        int k = tid + kq*256;
        const float* e = emb + (size_t)k*HH;
        float s = 0.f, dt = 0.f;
        for (int jj = 0; jj < HH; jj++){ float ev = e[jj]; s += ev*ev; dt += ev*zs[jj]; }
        float score = s - 2.f*dt;
        if (score < bestS || (score == bestS && k < bestK)){ bestS = score; bestK = k; }
    }
    rs[tid] = bestS; rk[tid] = bestK;
    __syncthreads();
    for (int s = 128; s > 0; s >>= 1){
        if (tid < s){
            if (rs[tid+s] < rs[tid] || (rs[tid+s] == rs[tid] && rk[tid+s] < rk[tid])){
                rs[tid] = rs[tid+s]; rk[tid] = rk[tid+s];
            }
        }
        __syncthreads();
    }
    int idx = rk[0];
    if (tid == 0) g_idx[b] = idx;
    float lp = 0.f;
    #pragma unroll
    for (int kq = 0; kq < 2; kq++){
        int jj = tid + kq*256;
        float q = emb[(size_t)idx*HH + jj];
        g_quant[(size_t)b*HH + jj] = q;
        float dz = q - zs[jj];
        lp += dz*dz;
    }
    __syncthreads();
    rs[tid] = lp;
    __syncthreads();
    for (int s = 128; s > 0; s >>= 1){
        if (tid < s) rs[tid] += rs[tid+s];
        __syncthreads();
    }
    if (tid == 0) g_lossp[b] = rs[0];
}

__global__ void k_vqfinish(float* __restrict__ out){
    const size_t OFF = (size_t)BB*TT*DD;
    int tid = threadIdx.x;
    if (tid == 0){
        float tot = 0.f;
        for (int i = 0; i < BB; i++) tot += g_lossp[i];
        out[OFF] = 1.25f * tot / (float)(BB*HH);
    }
    out[OFF + 1 + tid] = (float)g_idx[tid];
}

// ---------------- recon head ----------------
__device__ __forceinline__ void stage_h32r(float hsb[32][68], const float* __restrict__ src, int stride){
    int kk = threadIdx.x & 31, rb = threadIdx.x >> 5;
    #pragma unroll
    for (int i = 0; i < 8; i++)
        hsb[kk][rb + i*8] = src[(size_t)(rb + i*8)*stride + kk];
}

__global__ void __launch_bounds__(256) k_recon(const float* __restrict__ fcW,
                                               const float* __restrict__ fcb,
                                               float* __restrict__ out){
    __shared__ __align__(16) float hsb[32][68];
    __shared__ unsigned long long wsd[32][DD];
    int t = blockIdx.x;
    int b0 = blockIdx.y * 64;
    int tid = threadIdx.x;
    int txd = tid & 15, tyb = tid >> 4;

    unsigned long long acc[5][2];
    #pragma unroll
    for (int s = 0; s < 5; s++){ acc[s][0] = 0ull; acc[s][1] = 0ull; }

    for (int c = 0; c < 16; c++){
        __syncthreads();
        stage_h32r(hsb, g_Hbuf + ((size_t)t*BB + b0)*HH + c*32, HH);
        {
            int kk = tid & 31, db = tid >> 5;
            #pragma unroll
            for (int i = 0; i < 10; i++){
                int d = db + i*8;
                wsd[kk][d] = dupf(fcW[(size_t)d*HH + c*32 + kk]);
            }
        }
        __syncthreads();
        #pragma unroll
        for (int kk = 0; kk < 32; kk++){
            ulonglong2 hp = *(const ulonglong2*)&hsb[kk][tyb*4];
            #pragma unroll
            for (int s = 0; s < 5; s++){
                unsigned long long w = wsd[kk][txd + 16*s];
                ffma2(acc[s][0], hp.x, w);
                ffma2(acc[s][1], hp.y, w);
            }
        }
    }
    #pragma unroll
    for (int s = 0; s < 5; s++){
        int d = txd + 16*s;
        float bv = fcb[d];
        #pragma unroll
        for (int p = 0; p < 2; p++){
            float2 v = ull2f(acc[s][p]);
            int b = b0 + tyb*4 + p*2;
            out[((size_t)b*TT + t)*DD + d]     = v.x + bv;
            out[((size_t)(b+1)*TT + t)*DD + d] = v.y + bv;
        }
    }
}

// ---------------- launcher ----------------
extern "C" void kernel_launch(void* const* d_in, const int* in_sizes, int n_in,
                              void* d_out, int out_size){
    (void)in_sizes; (void)n_in; (void)out_size;
    const float* traj = (const float*)d_in[0];
    const float* eWih = (const float*)d_in[2];
    const float* eWhh = (const float*)d_in[3];
    const float* ebi  = (const float*)d_in[4];
    const float* ebh  = (const float*)d_in[5];
    const float* emb  = (const float*)d_in[6];
    const float* dWih = (const float*)d_in[7];
    const float* dWhh = (const float*)d_in[8];
    const float* dbi  = (const float*)d_in[9];
    const float* dbh  = (const float*)d_in[10];
    const float* fcW  = (const float*)d_in[11];
    const float* fcb  = (const float*)d_in[12];
    float* out = (float*)d_out;

    const int SME = 133120 + 11264 + 11264 + 4*17408;  // 225280 B
    const int SMD = 66560 + 4*17408;                   // 136192 B
    cudaFuncSetAttribute(k_rnn<true>,  cudaFuncAttributeMaxDynamicSharedMemorySize, SME);
    cudaFuncSetAttribute(k_rnn<false>, cudaFuncAttributeMaxDynamicSharedMemorySize, SMD);

    k_bias<<<8, 256>>>(ebi, ebh, dbi, dbh, dWih, fcb);
    k_wcomb<<<512, 256>>>(dWih, dWhh, fcW);
    k_tx<<<1024, 256>>>(traj);
    k_rnn<true><<<NBLK, 256, SME>>>(eWih, eWhh);   // launch #4 -> ncu capture slot
    k_vq<<<BB, 256>>>(emb);
    k_vqfinish<<<1, 256>>>(out);
    k_x1<<<BB, 256>>>(fcW, fcb);
    k_corr<<<GG, 256>>>(dWih);
    k_decprep<<<512, 256>>>();
    k_rnn<false><<<NBLK, 256, SMD>>>(eWih, eWhh);
    k_recon<<<dim3(TT, 4), 256>>>(fcW, fcb, out);
}

// round 11
// speedup vs baseline: 1.3413x; 1.2773x over previous
#include <cuda_runtime.h>
#include <cuda_fp16.h>
#include <cstdint>

#define BB 256
#define TT 256
#define DD 80
#define HH 512
#define GG 2048
#define NBLK 128
#define CS 136                 // h chunk smem stride (halves)

// ---------------- device scratch ----------------
__device__ __align__(16) __half g_h16[2][(size_t)BB*HH]; // [parity]
__device__ __align__(16) __half g_txh[(size_t)BB*TT*DD];
__device__ float g_Wcomb[(size_t)GG*HH];
__device__ float g_bias_enc[GG];
__device__ float g_bcomb[GG];
__device__ float g_quant[BB*HH];
__device__ float g_hA[BB*HH];
__device__ float g_tmpT[DD*BB];
__device__ float g_corr[(size_t)BB*GG];
__device__ float g_lossp[BB];
__device__ int   g_idx[BB];
__device__ float g_Hbuf[(size_t)TT*BB*HH];
__device__ unsigned g_bar;

// ---------------- helpers ----------------
__device__ __forceinline__ unsigned long long dupf(float v){
    unsigned long long r; asm("mov.b64 %0, {%1,%1};" : "=l"(r) : "f"(v)); return r;
}
__device__ __forceinline__ float2 ull2f(unsigned long long v){
    float2 r; asm("mov.b64 {%0,%1}, %2;" : "=f"(r.x), "=f"(r.y) : "l"(v)); return r;
}
__device__ __forceinline__ void ffma2(unsigned long long& d, unsigned long long a, unsigned long long b){
    asm("fma.rn.f32x2 %0, %1, %2, %0;" : "+l"(d) : "l"(a), "l"(b));
}
__device__ __forceinline__ float sigf(float x){ return __fdividef(1.f, 1.f + __expf(-x)); }
__device__ __forceinline__ float tanh_f(float x){ return __fdividef(2.f, 1.f + __expf(-2.f*x)) - 1.f; }

__device__ __forceinline__ void cpa16s(uint32_t dst, const void* src){
    asm volatile("cp.async.cg.shared.global [%0], [%1], 16;" :: "r"(dst), "l"(src));
}
__device__ __forceinline__ void cpa_commit(){ asm volatile("cp.async.commit_group;" ::: "memory"); }
__device__ __forceinline__ void cpa_wait0(){ asm volatile("cp.async.wait_group 0;" ::: "memory"); }
__device__ __forceinline__ void cpa_wait1(){ asm volatile("cp.async.wait_group 1;" ::: "memory"); }

__device__ __forceinline__ void ldsm4(uint32_t* r, uint32_t addr){
    asm volatile("ldmatrix.sync.aligned.m8n8.x4.shared.b16 {%0,%1,%2,%3}, [%4];"
        : "=r"(r[0]), "=r"(r[1]), "=r"(r[2]), "=r"(r[3]) : "r"(addr));
}
__device__ __forceinline__ void hmma(float* c, const uint32_t* a, const uint32_t* b){
    asm volatile("mma.sync.aligned.m16n8k16.row.col.f32.f16.f16.f32 "
        "{%0,%1,%2,%3}, {%4,%5,%6,%7}, {%8,%9}, {%0,%1,%2,%3};"
        : "+f"(c[0]), "+f"(c[1]), "+f"(c[2]), "+f"(c[3])
        : "r"(a[0]), "r"(a[1]), "r"(a[2]), "r"(a[3]), "r"(b[0]), "r"(b[1]));
}

__device__ __forceinline__ void grid_sync(unsigned epoch){
    __syncthreads();
    if (threadIdx.x == 0){
        __threadfence();
        atomicAdd(&g_bar, 1u);
        unsigned target = (epoch + 1u) * NBLK;
        unsigned v;
        do {
            asm volatile("ld.acquire.gpu.u32 %0, [%1];" : "=r"(v) : "l"(&g_bar) : "memory");
        } while (v < target);
    }
    __syncthreads();
}

// MMA over one chunk: acc[gate][4]. LO selects 2-term (hi+lo W) vs 1-term.
template<int NK, int SW, bool LO>
__device__ __forceinline__ void mma_loop(float acc[4][4], uint32_t aA,
                                         uint32_t bH, uint32_t bL){
    #pragma unroll
    for (int kk = 0; kk < NK; kk++){
        uint32_t ah[4], bh0[4], bh1[4];
        ldsm4(ah,  aA + kk*32);
        ldsm4(bh0, bH + kk*32);
        ldsm4(bh1, bH + 16*SW*2 + kk*32);
        hmma(acc[0], ah, bh0);   hmma(acc[1], ah, bh0+2);
        hmma(acc[2], ah, bh1);   hmma(acc[3], ah, bh1+2);
        if (LO){
            uint32_t bl0[4], bl1[4];
            ldsm4(bl0, bL + kk*32);
            ldsm4(bl1, bL + 16*SW*2 + kk*32);
            hmma(acc[0], ah, bl0);   hmma(acc[1], ah, bl0+2);
            hmma(acc[2], ah, bl1);   hmma(acc[3], ah, bl1+2);
        }
    }
}

// ---------------- prep kernels ----------------
__global__ void k_bias(const float* __restrict__ ebi, const float* __restrict__ ebh,
                       const float* __restrict__ dbi, const float* __restrict__ dbh,
                       const float* __restrict__ dWih, const float* __restrict__ fcb){
    int n = blockIdx.x*blockDim.x + threadIdx.x;
    if (n < GG){
        g_bias_enc[n] = ebi[n] + ebh[n];
        float b = dbi[n] + dbh[n];
        const float* w = dWih + (size_t)n*DD;
        #pragma unroll 4
        for (int d = 0; d < DD; d++) b += fcb[d]*w[d];
        g_bcomb[n] = b;
    }
}

__global__ void k_wcomb(const float* __restrict__ dWih, const float* __restrict__ dWhh,
                        const float* __restrict__ fcW){
    __shared__ float sf[DD][64];
    __shared__ float sw[32][DD];
    int nt = blockIdx.x >> 3, kt = blockIdx.x & 7;
    int n0 = nt*32, k0 = kt*64;
    int tid = threadIdx.x;
    for (int idx = tid; idx < DD*64; idx += 256){
        int d = idx >> 6, kk = idx & 63;
        sf[d][kk] = fcW[(size_t)d*HH + k0 + kk];
    }
    for (int idx = tid; idx < 32*DD; idx += 256){
        int nn = idx / DD, d = idx % DD;
        sw[nn][d] = dWih[(size_t)(n0+nn)*DD + d];
    }
    __syncthreads();
    int nn = tid >> 3, kb = (tid & 7)*8;
    float a[8];
    #pragma unroll
    for (int i = 0; i < 8; i++) a[i] = dWhh[(size_t)(n0+nn)*HH + k0 + kb + i];
    for (int d = 0; d < DD; d++){
        float w = sw[nn][d];
        #pragma unroll
        for (int i = 0; i < 8; i++) a[i] += w * sf[d][kb+i];
    }
    #pragma unroll
    for (int i = 0; i < 8; i++) g_Wcomb[(size_t)(n0+nn)*HH + k0 + kb + i] = a[i];
}

__global__ void k_tx(const float* __restrict__ traj){
    size_t N = (size_t)BB*TT*DD;
    for (size_t i = (size_t)blockIdx.x*blockDim.x + threadIdx.x; i < N; i += (size_t)gridDim.x*blockDim.x)
        g_txh[i] = __float2half_rn(traj[i]);
}

__global__ void k_x1(const float* __restrict__ fcW, const float* __restrict__ fcb){
    int b = blockIdx.x, tid = threadIdx.x;
    __shared__ float qs[HH];
    qs[tid]       = g_quant[(size_t)b*HH + tid];
    qs[tid + 256] = g_quant[(size_t)b*HH + tid + 256];
    __syncthreads();
    if (tid < DD){
        const float* w = fcW + (size_t)tid*HH;
        float s = fcb[tid];
        for (int k = 0; k < HH; k++) s += w[k]*qs[k];
        g_tmpT[tid*BB + b] = s;
    }
}

__global__ void k_corr(const float* __restrict__ dWih){
    int n = blockIdx.x, b = threadIdx.x;
    __shared__ float wd[DD];
    if (b < DD) wd[b] = dWih[(size_t)n*DD + b];
    __syncthreads();
    float s = 0.f;
    #pragma unroll 4
    for (int d = 0; d < DD; d++) s += wd[d] * g_tmpT[d*BB + b];
    g_corr[(size_t)b*GG + n] = s;
}

__global__ void k_init(){ if (threadIdx.x == 0 && blockIdx.x == 0) g_bar = 0u; }

__global__ void k_decprep(){
    int i = blockIdx.x*blockDim.x + threadIdx.x;
    if (i < BB*HH) g_h16[0][i] = __float2half_rn(g_quant[i]);
    if (i == 0) g_bar = 0u;
}

// ---------------- persistent recurrent kernel ----------------
// Block: 64 batch rows x 64 gate-cols (16 j x 4 gates). 8 warps = 4M x 2N.
// Enc: 2-term fp16-split W over K=592 (h 512 + x 80 unified).
// Dec: 1-term (Wcomb hi only). Per-chunk 3-buffer cp.async pipeline + grid barrier.
template<bool ENC>
__global__ void __launch_bounds__(256, 1) k_rnn(const float* __restrict__ eWih,
                                                const float* __restrict__ eWhh){
    extern __shared__ __half smh[];
    constexpr int SW = ENC ? 600 : 520;
    constexpr int KW = ENC ? 592 : 512;
    constexpr int NC = ENC ? 5 : 4;
    const uint32_t WREG = (uint32_t)(64*SW*2);           // bytes per W copy
    const uint32_t HS_OFF = (ENC ? 2u : 1u)*WREG;
    const uint32_t BUFB = (uint32_t)(64*CS*2);

    const int tid = threadIdx.x;
    const int wid = tid >> 5, lane = tid & 31;
    const int wm = wid & 3, wn = wid >> 2;
    const int rg = blockIdx.x >> 5, cg = blockIdx.x & 31;
    const int row0 = rg*64, j0 = cg*16;
    const uint32_t smb = (uint32_t)__cvta_generic_to_shared(smh);

    // ---- W fill (enc: hi+lo split; dec: hi only) ----
    for (int idx = tid; idx < 64*KW; idx += 256){
        int br = idx / KW, k = idx - br*KW;
        int n = ((br >> 3) & 3)*HH + j0 + (br >> 5)*8 + (br & 7);
        float v;
        if (ENC) v = (k < HH) ? eWhh[(size_t)n*HH + k] : eWih[(size_t)n*DD + k - HH];
        else     v = g_Wcomb[(size_t)n*HH + k];
        __half h = __float2half_rn(v);
        smh[br*SW + k] = h;
        if (ENC) smh[64*SW + br*SW + k] = __float2half_rn(v - __half2float(h));
    }

    const int j0w = j0 + wn*8;
    const int jj = (lane & 3)*2;
    const int rbase = row0 + wm*16 + (lane >> 2);
    float bias[4][2], corr[2][4][2];
    #pragma unroll
    for (int q = 0; q < 4; q++)
        #pragma unroll
        for (int e = 0; e < 2; e++){
            bias[q][e] = ENC ? g_bias_enc[q*HH + j0w + jj + e] : g_bcomb[q*HH + j0w + jj + e];
            if (!ENC){
                corr[0][q][e] = g_corr[(size_t)rbase*GG + q*HH + j0w + jj + e];
                corr[1][q][e] = g_corr[(size_t)(rbase+8)*GG + q*HH + j0w + jj + e];
            }
        }
    float cst[2][2] = {{0.f,0.f},{0.f,0.f}};

    const uint32_t laneA = (uint32_t)((wm*16 + (lane & 15))*CS + (lane >> 4)*8)*2;
    const uint32_t laneB = (uint32_t)(((lane & 7) + ((lane >> 4) & 1)*8 + wn*32)*SW + ((lane >> 3) & 1)*8)*2;

    // stage chunk c of step t into buffer buf
    auto stage = [&](int buf, int c, int t){
        uint32_t dst = smb + HS_OFF + (uint32_t)buf*BUFB;
        if (ENC && c == 0){
            #pragma unroll
            for (int i = 0; i < 3; i++){
                int u = tid + i*256;
                if (u < 640){
                    int r = u/10, s = u - r*10;
                    cpa16s(dst + (uint32_t)(r*CS + s*16 - r*CS + r*CS)*0 + (uint32_t)(r*CS*2 + s*16),
                           g_txh + ((size_t)(row0+r)*TT + t)*DD + s*8);
                }
            }
        } else {
            const __half* src = g_h16[t & 1];
            int kb = ENC ? (c-1)*128 : c*128;
            #pragma unroll
            for (int i = 0; i < 4; i++){
                int u = tid + i*256;
                int r = u >> 4, s = u & 15;
                cpa16s(dst + (uint32_t)(r*CS*2 + s*16),
                       src + (size_t)(row0+r)*HH + kb + s*8);
            }
        }
        cpa_commit();
    };

    __syncthreads();
    if (ENC) stage(0, 0, 0);   // x(0), nothing depends on h

    for (int t = 0; t < TT; t++){
        if (!ENC) stage(0, 0, t);
        const int nc = (ENC && t == 0) ? 1 : NC;
        if (nc > 1) stage(1, 1, t);

        float acc[4][4];
        #pragma unroll
        for (int q = 0; q < 4; q++)
            #pragma unroll
            for (int i = 0; i < 4; i++) acc[q][i] = 0.f;

        for (int c = 0; c < nc; c++){
            if (c < nc-1) cpa_wait1(); else cpa_wait0();
            __syncthreads();
            if (c + 2 < nc) stage((c+2)%3, c+2, t);
            {
                uint32_t aA = smb + HS_OFF + (uint32_t)(c%3)*BUFB + laneA;
                int koff = (ENC && c == 0) ? 512 : (ENC ? (c-1)*128 : c*128);
                uint32_t bH = smb + laneB + (uint32_t)koff*2;
                uint32_t bL = bH + WREG;
                if (ENC && c == 0) mma_loop<5, SW, true >(acc, aA, bH, bL);
                else if (ENC)      mma_loop<8, SW, true >(acc, aA, bH, bL);
                else               mma_loop<8, SW, false>(acc, aA, bH, bL);
            }
        }
        __syncthreads();

        // ---- epilogue ----
        {
            const int nimg = (t+1) & 1;
            #pragma unroll
            for (int p = 0; p < 2; p++){
                float hv[2];
                #pragma unroll
                for (int e = 0; e < 2; e++){
                    float gi = acc[0][p*2+e] + bias[0][e];
                    float gf = acc[1][p*2+e] + bias[1][e];
                    float gg = acc[2][p*2+e] + bias[2][e];
                    float go = acc[3][p*2+e] + bias[3][e];
                    if (!ENC && t == 0){
                        gi -= corr[p][0][e]; gf -= corr[p][1][e];
                        gg -= corr[p][2][e]; go -= corr[p][3][e];
                    }
                    float cn = sigf(gf)*cst[p][e] + sigf(gi)*tanh_f(gg);
                    cst[p][e] = cn;
                    hv[e] = sigf(go)*tanh_f(cn);
                }
                int r = rbase + p*8;
                __half h0 = __float2half_rn(hv[0]);
                __half h1 = __float2half_rn(hv[1]);
                uint32_t uh = (uint32_t)__half_as_ushort(h0) | ((uint32_t)__half_as_ushort(h1) << 16);
                *(uint32_t*)&g_h16[nimg][(size_t)r*HH + j0w + jj] = uh;
                if (ENC){
                    if (t == TT-1){
                        g_hA[(size_t)r*HH + j0w + jj]     = hv[0];
                        g_hA[(size_t)r*HH + j0w + jj + 1] = hv[1];
                    }
                } else {
                    float2 f2; f2.x = hv[0]; f2.y = hv[1];
                    *(float2*)&g_Hbuf[((size_t)t*BB + r)*HH + j0w + jj] = f2;
                }
            }
        }
        if (ENC && t + 1 < TT) stage(0, 0, t+1);   // x(t+1) across the barrier
        grid_sync((unsigned)t);
    }
}

// ---------------- VQ ----------------
__global__ void k_vq(const float* __restrict__ emb){
    int b = blockIdx.x, tid = threadIdx.x;
    __shared__ float zs[HH];
    __shared__ float rs[256];
    __shared__ int   rk[256];
    zs[tid]       = g_hA[(size_t)b*HH + tid];
    zs[tid + 256] = g_hA[(size_t)b*HH + tid + 256];
    __syncthreads();
    float bestS = 3.4e38f; int bestK = 0;
    #pragma unroll
    for (int kq = 0; kq < 2; kq++){
        int k = tid + kq*256;
        const float* e = emb + (size_t)k*HH;
        float s = 0.f, dt = 0.f;
        for (int jj = 0; jj < HH; jj++){ float ev = e[jj]; s += ev*ev; dt += ev*zs[jj]; }
        float score = s - 2.f*dt;
        if (score < bestS || (score == bestS && k < bestK)){ bestS = score; bestK = k; }
    }
    rs[tid] = bestS; rk[tid] = bestK;
    __syncthreads();
    for (int s = 128; s > 0; s >>= 1){
        if (tid < s){
            if (rs[tid+s] < rs[tid] || (rs[tid+s] == rs[tid] && rk[tid+s] < rk[tid])){
                rs[tid] = rs[tid+s]; rk[tid] = rk[tid+s];
            }
        }
        __syncthreads();
    }
    int idx = rk[0];
    if (tid == 0) g_idx[b] = idx;
    float lp = 0.f;
    #pragma unroll
    for (int kq = 0; kq < 2; kq++){
        int jj = tid + kq*256;
        float q = emb[(size_t)idx*HH + jj];
        g_quant[(size_t)b*HH + jj] = q;
        float dz = q - zs[jj];
        lp += dz*dz;
    }
    __syncthreads();
    rs[tid] = lp;
    __syncthreads();
    for (int s = 128; s > 0; s >>= 1){
        if (tid < s) rs[tid] += rs[tid+s];
        __syncthreads();
    }
    if (tid == 0) g_lossp[b] = rs[0];
}

__global__ void k_vqfinish(float* __restrict__ out){
    const size_t OFF = (size_t)BB*TT*DD;
    int tid = threadIdx.x;
    if (tid == 0){
        float tot = 0.f;
        for (int i = 0; i < BB; i++) tot += g_lossp[i];
        out[OFF] = 1.25f * tot / (float)(BB*HH);
    }
    out[OFF + 1 + tid] = (float)g_idx[tid];
}

// ---------------- recon head ----------------
__device__ __forceinline__ void stage_h32r(float hsb[32][68], const float* __restrict__ src, int stride){
    int kk = threadIdx.x & 31, rb = threadIdx.x >> 5;
    #pragma unroll
    for (int i = 0; i < 8; i++)
        hsb[kk][rb + i*8] = src[(size_t)(rb + i*8)*stride + kk];
}

__global__ void __launch_bounds__(256) k_recon(const float* __restrict__ fcW,
                                               const float* __restrict__ fcb,
                                               float* __restrict__ out){
    __shared__ __align__(16) float hsb[32][68];
    __shared__ unsigned long long wsd[32][DD];
    int t = blockIdx.x;
    int b0 = blockIdx.y * 64;
    int tid = threadIdx.x;
    int txd = tid & 15, tyb = tid >> 4;

    unsigned long long acc[5][2];
    #pragma unroll
    for (int s = 0; s < 5; s++){ acc[s][0] = 0ull; acc[s][1] = 0ull; }

    for (int c = 0; c < 16; c++){
        __syncthreads();
        stage_h32r(hsb, g_Hbuf + ((size_t)t*BB + b0)*HH + c*32, HH);
        {
            int kk = tid & 31, db = tid >> 5;
            #pragma unroll
            for (int i = 0; i < 10; i++){
                int d = db + i*8;
                wsd[kk][d] = dupf(fcW[(size_t)d*HH + c*32 + kk]);
            }
        }
        __syncthreads();
        #pragma unroll
        for (int kk = 0; kk < 32; kk++){
            ulonglong2 hp = *(const ulonglong2*)&hsb[kk][tyb*4];
            #pragma unroll
            for (int s = 0; s < 5; s++){
                unsigned long long w = wsd[kk][txd + 16*s];
                ffma2(acc[s][0], hp.x, w);
                ffma2(acc[s][1], hp.y, w);
            }
        }
    }
    #pragma unroll
    for (int s = 0; s < 5; s++){
        int d = txd + 16*s;
        float bv = fcb[d];
        #pragma unroll
        for (int p = 0; p < 2; p++){
            float2 v = ull2f(acc[s][p]);
            int b = b0 + tyb*4 + p*2;
            out[((size_t)b*TT + t)*DD + d]     = v.x + bv;
            out[((size_t)(b+1)*TT + t)*DD + d] = v.y + bv;
        }
    }
}

// ---------------- launcher ----------------
extern "C" void kernel_launch(void* const* d_in, const int* in_sizes, int n_in,
                              void* d_out, int out_size){
    (void)in_sizes; (void)n_in; (void)out_size;
    const float* traj = (const float*)d_in[0];
    const float* eWih = (const float*)d_in[2];
    const float* eWhh = (const float*)d_in[3];
    const float* ebi  = (const float*)d_in[4];
    const float* ebh  = (const float*)d_in[5];
    const float* emb  = (const float*)d_in[6];
    const float* dWih = (const float*)d_in[7];
    const float* dWhh = (const float*)d_in[8];
    const float* dbi  = (const float*)d_in[9];
    const float* dbh  = (const float*)d_in[10];
    const float* fcW  = (const float*)d_in[11];
    const float* fcb  = (const float*)d_in[12];
    float* out = (float*)d_out;

    const int SME = (2*64*600 + 3*64*CS)*2;   // 205824 B
    const int SMD = (1*64*520 + 3*64*CS)*2;   // 118784 B
    cudaFuncSetAttribute(k_rnn<true>,  cudaFuncAttributeMaxDynamicSharedMemorySize, SME);
    cudaFuncSetAttribute(k_rnn<false>, cudaFuncAttributeMaxDynamicSharedMemorySize, SMD);

    k_bias<<<8, 256>>>(ebi, ebh, dbi, dbh, dWih, fcb);
    k_wcomb<<<512, 256>>>(dWih, dWhh, fcW);
    k_tx<<<1024, 256>>>(traj);
    k_init<<<1, 32>>>();
    k_rnn<true><<<NBLK, 256, SME>>>(eWih, eWhh);
    k_vq<<<BB, 256>>>(emb);
    k_vqfinish<<<1, 256>>>(out);
    k_x1<<<BB, 256>>>(fcW, fcb);
    k_corr<<<GG, 256>>>(dWih);
    k_decprep<<<512, 256>>>();
    k_rnn<false><<<NBLK, 256, SMD>>>(eWih, eWhh);
    k_recon<<<dim3(TT, 4), 256>>>(fcW, fcb, out);
}

// round 12
// speedup vs baseline: 1.4870x; 1.1087x over previous
#include <cuda_runtime.h>
#include <cuda_fp16.h>
#include <cstdint>

#define BB 256
#define TT 256
#define DD 80
#define HH 512
#define GG 2048
#define NBLK 128
#define CS 136                 // h chunk smem stride (halves)

// ---------------- device scratch ----------------
__device__ __align__(16) __half g_h16[2][(size_t)BB*HH]; // [parity]
__device__ __align__(16) __half g_txh[(size_t)BB*TT*DD];
__device__ float g_Wcomb[(size_t)GG*HH];
__device__ float g_bias_enc[GG];
__device__ float g_bcomb[GG];
__device__ float g_quant[BB*HH];
__device__ float g_hA[BB*HH];
__device__ float g_tmpT[DD*BB];
__device__ float g_corr[(size_t)BB*GG];
__device__ float g_lossp[BB];
__device__ int   g_idx[BB];
__device__ float g_Hbuf[(size_t)TT*BB*HH];
__device__ unsigned g_bar;

// ---------------- helpers ----------------
__device__ __forceinline__ unsigned long long dupf(float v){
    unsigned long long r; asm("mov.b64 %0, {%1,%1};" : "=l"(r) : "f"(v)); return r;
}
__device__ __forceinline__ float2 ull2f(unsigned long long v){
    float2 r; asm("mov.b64 {%0,%1}, %2;" : "=f"(r.x), "=f"(r.y) : "l"(v)); return r;
}
__device__ __forceinline__ void ffma2(unsigned long long& d, unsigned long long a, unsigned long long b){
    asm("fma.rn.f32x2 %0, %1, %2, %0;" : "+l"(d) : "l"(a), "l"(b));
}
__device__ __forceinline__ float sigf(float x){ return __fdividef(1.f, 1.f + __expf(-x)); }
__device__ __forceinline__ float tanh_f(float x){ return __fdividef(2.f, 1.f + __expf(-2.f*x)) - 1.f; }

__device__ __forceinline__ void cpa16s(uint32_t dst, const void* src){
    asm volatile("cp.async.cg.shared.global [%0], [%1], 16;" :: "r"(dst), "l"(src));
}
__device__ __forceinline__ void cpa_commit(){ asm volatile("cp.async.commit_group;" ::: "memory"); }
__device__ __forceinline__ void cpa_wait0(){ asm volatile("cp.async.wait_group 0;" ::: "memory"); }
__device__ __forceinline__ void cpa_wait1(){ asm volatile("cp.async.wait_group 1;" ::: "memory"); }

__device__ __forceinline__ void ldsm4(uint32_t* r, uint32_t addr){
    asm volatile("ldmatrix.sync.aligned.m8n8.x4.shared.b16 {%0,%1,%2,%3}, [%4];"
        : "=r"(r[0]), "=r"(r[1]), "=r"(r[2]), "=r"(r[3]) : "r"(addr));
}
__device__ __forceinline__ void hmma(float* c, const uint32_t* a, const uint32_t* b){
    asm volatile("mma.sync.aligned.m16n8k16.row.col.f32.f16.f16.f32 "
        "{%0,%1,%2,%3}, {%4,%5,%6,%7}, {%8,%9}, {%0,%1,%2,%3};"
        : "+f"(c[0]), "+f"(c[1]), "+f"(c[2]), "+f"(c[3])
        : "r"(a[0]), "r"(a[1]), "r"(a[2]), "r"(a[3]), "r"(b[0]), "r"(b[1]));
}

__device__ __forceinline__ void grid_sync(unsigned epoch){
    __syncthreads();
    if (threadIdx.x == 0){
        asm volatile("red.release.gpu.global.add.u32 [%0], %1;" :: "l"(&g_bar), "r"(1u) : "memory");
        unsigned target = (epoch + 1u) * NBLK;
        unsigned v;
        do {
            asm volatile("ld.acquire.gpu.u32 %0, [%1];" : "=r"(v) : "l"(&g_bar) : "memory");
        } while (v < target);
    }
    __syncthreads();
}

// 1-term MMA over one chunk: acc[gate][4]
template<int NK, int SW>
__device__ __forceinline__ void mma_loop(float acc[4][4], uint32_t aA, uint32_t bH){
    #pragma unroll
    for (int kk = 0; kk < NK; kk++){
        uint32_t ah[4], bh0[4], bh1[4];
        ldsm4(ah,  aA + kk*32);
        ldsm4(bh0, bH + kk*32);
        ldsm4(bh1, bH + 16*SW*2 + kk*32);
        hmma(acc[0], ah, bh0);   hmma(acc[1], ah, bh0+2);
        hmma(acc[2], ah, bh1);   hmma(acc[3], ah, bh1+2);
    }
}

// ---------------- prep kernels ----------------
__global__ void k_bias(const float* __restrict__ ebi, const float* __restrict__ ebh,
                       const float* __restrict__ dbi, const float* __restrict__ dbh,
                       const float* __restrict__ dWih, const float* __restrict__ fcb){
    int n = blockIdx.x*blockDim.x + threadIdx.x;
    if (n < GG){
        g_bias_enc[n] = ebi[n] + ebh[n];
        float b = dbi[n] + dbh[n];
        const float* w = dWih + (size_t)n*DD;
        #pragma unroll 4
        for (int d = 0; d < DD; d++) b += fcb[d]*w[d];
        g_bcomb[n] = b;
    }
}

__global__ void k_wcomb(const float* __restrict__ dWih, const float* __restrict__ dWhh,
                        const float* __restrict__ fcW){
    __shared__ float sf[DD][64];
    __shared__ float sw[32][DD];
    int nt = blockIdx.x >> 3, kt = blockIdx.x & 7;
    int n0 = nt*32, k0 = kt*64;
    int tid = threadIdx.x;
    for (int idx = tid; idx < DD*64; idx += 256){
        int d = idx >> 6, kk = idx & 63;
        sf[d][kk] = fcW[(size_t)d*HH + k0 + kk];
    }
    for (int idx = tid; idx < 32*DD; idx += 256){
        int nn = idx / DD, d = idx % DD;
        sw[nn][d] = dWih[(size_t)(n0+nn)*DD + d];
    }
    __syncthreads();
    int nn = tid >> 3, kb = (tid & 7)*8;
    float a[8];
    #pragma unroll
    for (int i = 0; i < 8; i++) a[i] = dWhh[(size_t)(n0+nn)*HH + k0 + kb + i];
    for (int d = 0; d < DD; d++){
        float w = sw[nn][d];
        #pragma unroll
        for (int i = 0; i < 8; i++) a[i] += w * sf[d][kb+i];
    }
    #pragma unroll
    for (int i = 0; i < 8; i++) g_Wcomb[(size_t)(n0+nn)*HH + k0 + kb + i] = a[i];
}

__global__ void k_tx(const float* __restrict__ traj){
    if (blockIdx.x == 0 && threadIdx.x == 0) g_bar = 0u;
    size_t N = (size_t)BB*TT*DD;
    for (size_t i = (size_t)blockIdx.x*blockDim.x + threadIdx.x; i < N; i += (size_t)gridDim.x*blockDim.x)
        g_txh[i] = __float2half_rn(traj[i]);
}

__global__ void k_x1(const float* __restrict__ fcW, const float* __restrict__ fcb){
    int b = blockIdx.x, tid = threadIdx.x;
    __shared__ float qs[HH];
    qs[tid]       = g_quant[(size_t)b*HH + tid];
    qs[tid + 256] = g_quant[(size_t)b*HH + tid + 256];
    __syncthreads();
    if (tid < DD){
        const float* w = fcW + (size_t)tid*HH;
        float s = fcb[tid];
        for (int k = 0; k < HH; k++) s += w[k]*qs[k];
        g_tmpT[tid*BB + b] = s;
    }
}

__global__ void k_corr(const float* __restrict__ dWih){
    int n = blockIdx.x, b = threadIdx.x;
    __shared__ float wd[DD];
    if (b < DD) wd[b] = dWih[(size_t)n*DD + b];
    __syncthreads();
    float s = 0.f;
    #pragma unroll 4
    for (int d = 0; d < DD; d++) s += wd[d] * g_tmpT[d*BB + b];
    g_corr[(size_t)b*GG + n] = s;
}

__global__ void k_decprep(){
    int i = blockIdx.x*blockDim.x + threadIdx.x;
    if (i < BB*HH) g_h16[0][i] = __float2half_rn(g_quant[i]);
    if (i == 0) g_bar = 0u;
}

// ---------------- persistent recurrent kernel ----------------
// Block: 64 batch rows x 64 gate-cols (16 j x 4 gates). 8 warps = 4M x 2N.
// Both enc and dec: 1-term fp16 W (hi only).
// Per-chunk 3-buffer cp.async pipeline + release/acquire grid barrier.
template<bool ENC>
__global__ void __launch_bounds__(256, 1) k_rnn(const float* __restrict__ eWih,
                                                const float* __restrict__ eWhh){
    extern __shared__ __half smh[];
    constexpr int SW = ENC ? 600 : 520;
    constexpr int KW = ENC ? 592 : 512;
    constexpr int NC = ENC ? 5 : 4;
    const uint32_t WREG = (uint32_t)(64*SW*2);           // bytes for W
    const uint32_t HS_OFF = WREG;
    const uint32_t BUFB = (uint32_t)(64*CS*2);

    const int tid = threadIdx.x;
    const int wid = tid >> 5, lane = tid & 31;
    const int wm = wid & 3, wn = wid >> 2;
    const int rg = blockIdx.x >> 5, cg = blockIdx.x & 31;
    const int row0 = rg*64, j0 = cg*16;
    const uint32_t smb = (uint32_t)__cvta_generic_to_shared(smh);

    // ---- W fill (hi only) ----
    for (int idx = tid; idx < 64*KW; idx += 256){
        int br = idx / KW, k = idx - br*KW;
        int n = ((br >> 3) & 3)*HH + j0 + (br >> 5)*8 + (br & 7);
        float v;
        if (ENC) v = (k < HH) ? eWhh[(size_t)n*HH + k] : eWih[(size_t)n*DD + k - HH];
        else     v = g_Wcomb[(size_t)n*HH + k];
        smh[br*SW + k] = __float2half_rn(v);
    }

    const int j0w = j0 + wn*8;
    const int jj = (lane & 3)*2;
    const int rbase = row0 + wm*16 + (lane >> 2);
    float bias[4][2], corr[2][4][2];
    #pragma unroll
    for (int q = 0; q < 4; q++)
        #pragma unroll
        for (int e = 0; e < 2; e++){
            bias[q][e] = ENC ? g_bias_enc[q*HH + j0w + jj + e] : g_bcomb[q*HH + j0w + jj + e];
            if (!ENC){
                corr[0][q][e] = g_corr[(size_t)rbase*GG + q*HH + j0w + jj + e];
                corr[1][q][e] = g_corr[(size_t)(rbase+8)*GG + q*HH + j0w + jj + e];
            }
        }
    float cst[2][2] = {{0.f,0.f},{0.f,0.f}};

    const uint32_t laneA = (uint32_t)((wm*16 + (lane & 15))*CS + (lane >> 4)*8)*2;
    const uint32_t laneB = (uint32_t)(((lane & 7) + ((lane >> 4) & 1)*8 + wn*32)*SW + ((lane >> 3) & 1)*8)*2;

    // stage chunk c of step t into buffer buf
    auto stage = [&](int buf, int c, int t){
        uint32_t dst = smb + HS_OFF + (uint32_t)buf*BUFB;
        if (ENC && c == 0){
            #pragma unroll
            for (int i = 0; i < 3; i++){
                int u = tid + i*256;
                if (u < 640){
                    int r = u/10, s = u - r*10;
                    cpa16s(dst + (uint32_t)(r*CS*2 + s*16),
                           g_txh + ((size_t)(row0+r)*TT + t)*DD + s*8);
                }
            }
        } else {
            const __half* src = g_h16[t & 1];
            int kb = ENC ? (c-1)*128 : c*128;
            #pragma unroll
            for (int i = 0; i < 4; i++){
                int u = tid + i*256;
                int r = u >> 4, s = u & 15;
                cpa16s(dst + (uint32_t)(r*CS*2 + s*16),
                       src + (size_t)(row0+r)*HH + kb + s*8);
            }
        }
        cpa_commit();
    };

    __syncthreads();
    if (ENC) stage(0, 0, 0);   // x(0), nothing depends on h

    for (int t = 0; t < TT; t++){
        if (!ENC) stage(0, 0, t);
        const int nc = (ENC && t == 0) ? 1 : NC;
        if (nc > 1) stage(1, 1, t);

        float acc[4][4];
        #pragma unroll
        for (int q = 0; q < 4; q++)
            #pragma unroll
            for (int i = 0; i < 4; i++) acc[q][i] = 0.f;

        for (int c = 0; c < nc; c++){
            if (c < nc-1) cpa_wait1(); else cpa_wait0();
            __syncthreads();
            if (c + 2 < nc) stage((c+2)%3, c+2, t);
            {
                uint32_t aA = smb + HS_OFF + (uint32_t)(c%3)*BUFB + laneA;
                int koff = (ENC && c == 0) ? 512 : (ENC ? (c-1)*128 : c*128);
                uint32_t bH = smb + laneB + (uint32_t)koff*2;
                if (ENC && c == 0) mma_loop<5, SW>(acc, aA, bH);
                else               mma_loop<8, SW>(acc, aA, bH);
            }
        }
        __syncthreads();

        // ---- epilogue ----
        {
            const int nimg = (t+1) & 1;
            #pragma unroll
            for (int p = 0; p < 2; p++){
                float hv[2];
                #pragma unroll
                for (int e = 0; e < 2; e++){
                    float gi = acc[0][p*2+e] + bias[0][e];
                    float gf = acc[1][p*2+e] + bias[1][e];
                    float gg = acc[2][p*2+e] + bias[2][e];
                    float go = acc[3][p*2+e] + bias[3][e];
                    if (!ENC && t == 0){
                        gi -= corr[p][0][e]; gf -= corr[p][1][e];
                        gg -= corr[p][2][e]; go -= corr[p][3][e];
                    }
                    float cn = sigf(gf)*cst[p][e] + sigf(gi)*tanh_f(gg);
                    cst[p][e] = cn;
                    hv[e] = sigf(go)*tanh_f(cn);
                }
                int r = rbase + p*8;
                __half h0 = __float2half_rn(hv[0]);
                __half h1 = __float2half_rn(hv[1]);
                uint32_t uh = (uint32_t)__half_as_ushort(h0) | ((uint32_t)__half_as_ushort(h1) << 16);
                *(uint32_t*)&g_h16[nimg][(size_t)r*HH + j0w + jj] = uh;
                if (ENC){
                    if (t == TT-1){
                        g_hA[(size_t)r*HH + j0w + jj]     = hv[0];
                        g_hA[(size_t)r*HH + j0w + jj + 1] = hv[1];
                    }
                } else {
                    float2 f2; f2.x = hv[0]; f2.y = hv[1];
                    *(float2*)&g_Hbuf[((size_t)t*BB + r)*HH + j0w + jj] = f2;
                }
            }
        }
        if (ENC && t + 1 < TT) stage(0, 0, t+1);   // x(t+1) across the barrier
        grid_sync((unsigned)t);
    }
}

// ---------------- VQ ----------------
__global__ void k_vq(const float* __restrict__ emb){
    int b = blockIdx.x, tid = threadIdx.x;
    __shared__ float zs[HH];
    __shared__ float rs[256];
    __shared__ int   rk[256];
    zs[tid]       = g_hA[(size_t)b*HH + tid];
    zs[tid + 256] = g_hA[(size_t)b*HH + tid + 256];
    __syncthreads();
    float bestS = 3.4e38f; int bestK = 0;
    #pragma unroll
    for (int kq = 0; kq < 2; kq++){
        int k = tid + kq*256;
        const float* e = emb + (size_t)k*HH;
        float s = 0.f, dt = 0.f;
        for (int jj = 0; jj < HH; jj++){ float ev = e[jj]; s += ev*ev; dt += ev*zs[jj]; }
        float score = s - 2.f*dt;
        if (score < bestS || (score == bestS && k < bestK)){ bestS = score; bestK = k; }
    }
    rs[tid] = bestS; rk[tid] = bestK;
    __syncthreads();
    for (int s = 128; s > 0; s >>= 1){
        if (tid < s){
            if (rs[tid+s] < rs[tid] || (rs[tid+s] == rs[tid] && rk[tid+s] < rk[tid])){
                rs[tid] = rs[tid+s]; rk[tid] = rk[tid+s];
            }
        }
        __syncthreads();
    }
    int idx = rk[0];
    if (tid == 0) g_idx[b] = idx;
    float lp = 0.f;
    #pragma unroll
    for (int kq = 0; kq < 2; kq++){
        int jj = tid + kq*256;
        float q = emb[(size_t)idx*HH + jj];
        g_quant[(size_t)b*HH + jj] = q;
        float dz = q - zs[jj];
        lp += dz*dz;
    }
    __syncthreads();
    rs[tid] = lp;
    __syncthreads();
    for (int s = 128; s > 0; s >>= 1){
        if (tid < s) rs[tid] += rs[tid+s];
        __syncthreads();
    }
    if (tid == 0) g_lossp[b] = rs[0];
}

__global__ void k_vqfinish(float* __restrict__ out){
    const size_t OFF = (size_t)BB*TT*DD;
    int tid = threadIdx.x;
    if (tid == 0){
        float tot = 0.f;
        for (int i = 0; i < BB; i++) tot += g_lossp[i];
        out[OFF] = 1.25f * tot / (float)(BB*HH);
    }
    out[OFF + 1 + tid] = (float)g_idx[tid];
}

// ---------------- recon head ----------------
__device__ __forceinline__ void stage_h32r(float hsb[32][68], const float* __restrict__ src, int stride){
    int kk = threadIdx.x & 31, rb = threadIdx.x >> 5;
    #pragma unroll
    for (int i = 0; i < 8; i++)
        hsb[kk][rb + i*8] = src[(size_t)(rb + i*8)*stride + kk];
}

__global__ void __launch_bounds__(256) k_recon(const float* __restrict__ fcW,
                                               const float* __restrict__ fcb,
                                               float* __restrict__ out){
    __shared__ __align__(16) float hsb[32][68];
    __shared__ unsigned long long wsd[32][DD];
    int t = blockIdx.x;
    int b0 = blockIdx.y * 64;
    int tid = threadIdx.x;
    int txd = tid & 15, tyb = tid >> 4;

    unsigned long long acc[5][2];
    #pragma unroll
    for (int s = 0; s < 5; s++){ acc[s][0] = 0ull; acc[s][1] = 0ull; }

    for (int c = 0; c < 16; c++){
        __syncthreads();
        stage_h32r(hsb, g_Hbuf + ((size_t)t*BB + b0)*HH + c*32, HH);
        {
            int kk = tid & 31, db = tid >> 5;
            #pragma unroll
            for (int i = 0; i < 10; i++){
                int d = db + i*8;
                wsd[kk][d] = dupf(fcW[(size_t)d*HH + c*32 + kk]);
            }
        }
        __syncthreads();
        #pragma unroll
        for (int kk = 0; kk < 32; kk++){
            ulonglong2 hp = *(const ulonglong2*)&hsb[kk][tyb*4];
            #pragma unroll
            for (int s = 0; s < 5; s++){
                unsigned long long w = wsd[kk][txd + 16*s];
                ffma2(acc[s][0], hp.x, w);
                ffma2(acc[s][1], hp.y, w);
            }
        }
    }
    #pragma unroll
    for (int s = 0; s < 5; s++){
        int d = txd + 16*s;
        float bv = fcb[d];
        #pragma unroll
        for (int p = 0; p < 2; p++){
            float2 v = ull2f(acc[s][p]);
            int b = b0 + tyb*4 + p*2;
            out[((size_t)b*TT + t)*DD + d]     = v.x + bv;
            out[((size_t)(b+1)*TT + t)*DD + d] = v.y + bv;
        }
    }
}

// ---------------- launcher ----------------
extern "C" void kernel_launch(void* const* d_in, const int* in_sizes, int n_in,
                              void* d_out, int out_size){
    (void)in_sizes; (void)n_in; (void)out_size;
    const float* traj = (const float*)d_in[0];
    const float* eWih = (const float*)d_in[2];
    const float* eWhh = (const float*)d_in[3];
    const float* ebi  = (const float*)d_in[4];
    const float* ebh  = (const float*)d_in[5];
    const float* emb  = (const float*)d_in[6];
    const float* dWih = (const float*)d_in[7];
    const float* dWhh = (const float*)d_in[8];
    const float* dbi  = (const float*)d_in[9];
    const float* dbh  = (const float*)d_in[10];
    const float* fcW  = (const float*)d_in[11];
    const float* fcb  = (const float*)d_in[12];
    float* out = (float*)d_out;

    const int SME = (64*600 + 3*64*CS)*2;   // 129024 B
    const int SMD = (64*520 + 3*64*CS)*2;   // 118784 B
    cudaFuncSetAttribute(k_rnn<true>,  cudaFuncAttributeMaxDynamicSharedMemorySize, SME);
    cudaFuncSetAttribute(k_rnn<false>, cudaFuncAttributeMaxDynamicSharedMemorySize, SMD);

    k_bias<<<8, 256>>>(ebi, ebh, dbi, dbh, dWih, fcb);
    k_wcomb<<<512, 256>>>(dWih, dWhh, fcW);
    k_tx<<<1024, 256>>>(traj);
    k_rnn<true><<<NBLK, 256, SME>>>(eWih, eWhh);   // 4th launch -> ncu capture slot
    k_vq<<<BB, 256>>>(emb);
    k_vqfinish<<<1, 256>>>(out);
    k_x1<<<BB, 256>>>(fcW, fcb);
    k_corr<<<GG, 256>>>(dWih);
    k_decprep<<<512, 256>>>();
    k_rnn<false><<<NBLK, 256, SMD>>>(eWih, eWhh);
    k_recon<<<dim3(TT, 4), 256>>>(fcW, fcb, out);
}

// round 13
// speedup vs baseline: 1.5442x; 1.0384x over previous
#include <cuda_runtime.h>
#include <cuda_fp16.h>
#include <cstdint>

#define BB 256
#define TT 256
#define DD 80
#define HH 512
#define GG 2048
#define NBLK 256
#define NTH 128
#define CS 136                 // h chunk smem stride (halves)

// ---------------- device scratch ----------------
__device__ __align__(16) __half g_h16[2][(size_t)BB*HH]; // [parity]
__device__ __align__(16) __half g_txh[(size_t)BB*TT*DD];
__device__ float g_Wcomb[(size_t)GG*HH];
__device__ float g_bias_enc[GG];
__device__ float g_bcomb[GG];
__device__ float g_quant[BB*HH];
__device__ float g_hA[BB*HH];
__device__ float g_tmpT[DD*BB];
__device__ float g_corr[(size_t)BB*GG];
__device__ float g_lossp[BB];
__device__ int   g_idx[BB];
__device__ float g_Hbuf[(size_t)TT*BB*HH];
__device__ unsigned g_bar;

// ---------------- helpers ----------------
__device__ __forceinline__ unsigned long long dupf(float v){
    unsigned long long r; asm("mov.b64 %0, {%1,%1};" : "=l"(r) : "f"(v)); return r;
}
__device__ __forceinline__ float2 ull2f(unsigned long long v){
    float2 r; asm("mov.b64 {%0,%1}, %2;" : "=f"(r.x), "=f"(r.y) : "l"(v)); return r;
}
__device__ __forceinline__ void ffma2(unsigned long long& d, unsigned long long a, unsigned long long b){
    asm("fma.rn.f32x2 %0, %1, %2, %0;" : "+l"(d) : "l"(a), "l"(b));
}
__device__ __forceinline__ float sigf(float x){ return __fdividef(1.f, 1.f + __expf(-x)); }
__device__ __forceinline__ float tanh_f(float x){ return __fdividef(2.f, 1.f + __expf(-2.f*x)) - 1.f; }

__device__ __forceinline__ void cpa16s(uint32_t dst, const void* src){
    asm volatile("cp.async.cg.shared.global [%0], [%1], 16;" :: "r"(dst), "l"(src));
}
__device__ __forceinline__ void cpa_commit(){ asm volatile("cp.async.commit_group;" ::: "memory"); }
__device__ __forceinline__ void cpa_wait0(){ asm volatile("cp.async.wait_group 0;" ::: "memory"); }
__device__ __forceinline__ void cpa_wait1(){ asm volatile("cp.async.wait_group 1;" ::: "memory"); }

__device__ __forceinline__ void ldsm4(uint32_t* r, uint32_t addr){
    asm volatile("ldmatrix.sync.aligned.m8n8.x4.shared.b16 {%0,%1,%2,%3}, [%4];"
        : "=r"(r[0]), "=r"(r[1]), "=r"(r[2]), "=r"(r[3]) : "r"(addr));
}
__device__ __forceinline__ void hmma(float* c, const uint32_t* a, const uint32_t* b){
    asm volatile("mma.sync.aligned.m16n8k16.row.col.f32.f16.f16.f32 "
        "{%0,%1,%2,%3}, {%4,%5,%6,%7}, {%8,%9}, {%0,%1,%2,%3};"
        : "+f"(c[0]), "+f"(c[1]), "+f"(c[2]), "+f"(c[3])
        : "r"(a[0]), "r"(a[1]), "r"(a[2]), "r"(a[3]), "r"(b[0]), "r"(b[1]));
}

__device__ __forceinline__ void grid_sync(unsigned epoch){
    __syncthreads();
    if (threadIdx.x == 0){
        asm volatile("red.release.gpu.global.add.u32 [%0], %1;" :: "l"(&g_bar), "r"(1u) : "memory");
        unsigned target = (epoch + 1u) * NBLK;
        unsigned v;
        do {
            asm volatile("ld.acquire.gpu.u32 %0, [%1];" : "=r"(v) : "l"(&g_bar) : "memory");
        } while (v < target);
    }
    __syncthreads();
}

// 1-term MMA over one chunk: acc[gate][4]
template<int NK, int SW>
__device__ __forceinline__ void mma_loop(float acc[4][4], uint32_t aA, uint32_t bH){
    #pragma unroll
    for (int kk = 0; kk < NK; kk++){
        uint32_t ah[4], bh0[4], bh1[4];
        ldsm4(ah,  aA + kk*32);
        ldsm4(bh0, bH + kk*32);
        ldsm4(bh1, bH + 16*SW*2 + kk*32);
        hmma(acc[0], ah, bh0);   hmma(acc[1], ah, bh0+2);
        hmma(acc[2], ah, bh1);   hmma(acc[3], ah, bh1+2);
    }
}

// ---------------- prep kernels ----------------
__global__ void k_bias(const float* __restrict__ ebi, const float* __restrict__ ebh,
                       const float* __restrict__ dbi, const float* __restrict__ dbh,
                       const float* __restrict__ dWih, const float* __restrict__ fcb){
    int n = blockIdx.x*blockDim.x + threadIdx.x;
    if (n < GG){
        g_bias_enc[n] = ebi[n] + ebh[n];
        float b = dbi[n] + dbh[n];
        const float* w = dWih + (size_t)n*DD;
        #pragma unroll 4
        for (int d = 0; d < DD; d++) b += fcb[d]*w[d];
        g_bcomb[n] = b;
    }
}

__global__ void k_wcomb(const float* __restrict__ dWih, const float* __restrict__ dWhh,
                        const float* __restrict__ fcW){
    __shared__ float sf[DD][64];
    __shared__ float sw[32][DD];
    int nt = blockIdx.x >> 3, kt = blockIdx.x & 7;
    int n0 = nt*32, k0 = kt*64;
    int tid = threadIdx.x;
    for (int idx = tid; idx < DD*64; idx += 256){
        int d = idx >> 6, kk = idx & 63;
        sf[d][kk] = fcW[(size_t)d*HH + k0 + kk];
    }
    for (int idx = tid; idx < 32*DD; idx += 256){
        int nn = idx / DD, d = idx % DD;
        sw[nn][d] = dWih[(size_t)(n0+nn)*DD + d];
    }
    __syncthreads();
    int nn = tid >> 3, kb = (tid & 7)*8;
    float a[8];
    #pragma unroll
    for (int i = 0; i < 8; i++) a[i] = dWhh[(size_t)(n0+nn)*HH + k0 + kb + i];
    for (int d = 0; d < DD; d++){
        float w = sw[nn][d];
        #pragma unroll
        for (int i = 0; i < 8; i++) a[i] += w * sf[d][kb+i];
    }
    #pragma unroll
    for (int i = 0; i < 8; i++) g_Wcomb[(size_t)(n0+nn)*HH + k0 + kb + i] = a[i];
}

__global__ void k_tx(const float* __restrict__ traj){
    if (blockIdx.x == 0 && threadIdx.x == 0) g_bar = 0u;
    size_t N = (size_t)BB*TT*DD;
    for (size_t i = (size_t)blockIdx.x*blockDim.x + threadIdx.x; i < N; i += (size_t)gridDim.x*blockDim.x)
        g_txh[i] = __float2half_rn(traj[i]);
}

__global__ void k_x1(const float* __restrict__ fcW, const float* __restrict__ fcb){
    int b = blockIdx.x, tid = threadIdx.x;
    __shared__ float qs[HH];
    qs[tid]       = g_quant[(size_t)b*HH + tid];
    qs[tid + 256] = g_quant[(size_t)b*HH + tid + 256];
    __syncthreads();
    if (tid < DD){
        const float* w = fcW + (size_t)tid*HH;
        float s = fcb[tid];
        for (int k = 0; k < HH; k++) s += w[k]*qs[k];
        g_tmpT[tid*BB + b] = s;
    }
}

__global__ void k_corr(const float* __restrict__ dWih){
    int n = blockIdx.x, b = threadIdx.x;
    __shared__ float wd[DD];
    if (b < DD) wd[b] = dWih[(size_t)n*DD + b];
    __syncthreads();
    float s = 0.f;
    #pragma unroll 4
    for (int d = 0; d < DD; d++) s += wd[d] * g_tmpT[d*BB + b];
    g_corr[(size_t)b*GG + n] = s;
}

__global__ void k_decprep(){
    int i = blockIdx.x*blockDim.x + threadIdx.x;
    if (i < BB*HH) g_h16[0][i] = __float2half_rn(g_quant[i]);
    if (i == 0) g_bar = 0u;
}

// ---------------- persistent recurrent kernel ----------------
// Block: 32 batch rows x 64 gate-cols (16 j x 4 gates). 4 warps = 2M x 2N.
// Grid 256 = 8 rowgroups x 32 colgroups -> 2 CTAs/SM for latency overlap.
// Both enc and dec: 1-term fp16 W (hi only).
template<bool ENC>
__global__ void __launch_bounds__(NTH, 2) k_rnn(const float* __restrict__ eWih,
                                                const float* __restrict__ eWhh){
    extern __shared__ __half smh[];
    constexpr int SW = ENC ? 600 : 520;
    constexpr int KW = ENC ? 592 : 512;
    constexpr int NC = ENC ? 5 : 4;
    const uint32_t WREG = (uint32_t)(64*SW*2);           // bytes for W
    const uint32_t HS_OFF = WREG;
    const uint32_t BUFB = (uint32_t)(32*CS*2);

    const int tid = threadIdx.x;
    const int wid = tid >> 5, lane = tid & 31;
    const int wm = wid & 1, wn = wid >> 1;
    const int rg = blockIdx.x >> 5, cg = blockIdx.x & 31;
    const int row0 = rg*32, j0 = cg*16;
    const uint32_t smb = (uint32_t)__cvta_generic_to_shared(smh);

    // ---- W fill (hi only): 64 B-rows x KW ----
    for (int idx = tid; idx < 64*KW; idx += NTH){
        int br = idx / KW, k = idx - br*KW;
        int n = ((br >> 3) & 3)*HH + j0 + (br >> 5)*8 + (br & 7);
        float v;
        if (ENC) v = (k < HH) ? eWhh[(size_t)n*HH + k] : eWih[(size_t)n*DD + k - HH];
        else     v = g_Wcomb[(size_t)n*HH + k];
        smh[br*SW + k] = __float2half_rn(v);
    }

    const int j0w = j0 + wn*8;
    const int jj = (lane & 3)*2;
    const int rbase = row0 + wm*16 + (lane >> 2);
    float bias[4][2], corr[2][4][2];
    #pragma unroll
    for (int q = 0; q < 4; q++)
        #pragma unroll
        for (int e = 0; e < 2; e++){
            bias[q][e] = ENC ? g_bias_enc[q*HH + j0w + jj + e] : g_bcomb[q*HH + j0w + jj + e];
            if (!ENC){
                corr[0][q][e] = g_corr[(size_t)rbase*GG + q*HH + j0w + jj + e];
                corr[1][q][e] = g_corr[(size_t)(rbase+8)*GG + q*HH + j0w + jj + e];
            }
        }
    float cst[2][2] = {{0.f,0.f},{0.f,0.f}};

    const uint32_t laneA = (uint32_t)((wm*16 + (lane & 15))*CS + (lane >> 4)*8)*2;
    const uint32_t laneB = (uint32_t)(((lane & 7) + ((lane >> 4) & 1)*8 + wn*32)*SW + ((lane >> 3) & 1)*8)*2;

    // stage chunk c of step t into buffer buf (32 rows)
    auto stage = [&](int buf, int c, int t){
        uint32_t dst = smb + HS_OFF + (uint32_t)buf*BUFB;
        if (ENC && c == 0){
            #pragma unroll
            for (int i = 0; i < 3; i++){
                int u = tid + i*NTH;
                if (u < 320){
                    int r = u/10, s = u - r*10;
                    cpa16s(dst + (uint32_t)(r*CS*2 + s*16),
                           g_txh + ((size_t)(row0+r)*TT + t)*DD + s*8);
                }
            }
        } else {
            const __half* src = g_h16[t & 1];
            int kb = ENC ? (c-1)*128 : c*128;
            #pragma unroll
            for (int i = 0; i < 4; i++){
                int u = tid + i*NTH;
                int r = u >> 4, s = u & 15;
                cpa16s(dst + (uint32_t)(r*CS*2 + s*16),
                       src + (size_t)(row0+r)*HH + kb + s*8);
            }
        }
        cpa_commit();
    };

    __syncthreads();
    if (ENC) stage(0, 0, 0);   // x(0), nothing depends on h

    for (int t = 0; t < TT; t++){
        if (!ENC) stage(0, 0, t);
        const int nc = (ENC && t == 0) ? 1 : NC;
        if (nc > 1) stage(1, 1, t);

        float acc[4][4];
        #pragma unroll
        for (int q = 0; q < 4; q++)
            #pragma unroll
            for (int i = 0; i < 4; i++) acc[q][i] = 0.f;

        for (int c = 0; c < nc; c++){
            if (c < nc-1) cpa_wait1(); else cpa_wait0();
            __syncthreads();
            if (c + 2 < nc) stage((c+2)%3, c+2, t);
            {
                uint32_t aA = smb + HS_OFF + (uint32_t)(c%3)*BUFB + laneA;
                int koff = (ENC && c == 0) ? 512 : (ENC ? (c-1)*128 : c*128);
                uint32_t bH = smb + laneB + (uint32_t)koff*2;
                if (ENC && c == 0) mma_loop<5, SW>(acc, aA, bH);
                else               mma_loop<8, SW>(acc, aA, bH);
            }
        }
        __syncthreads();

        // ---- epilogue ----
        {
            const int nimg = (t+1) & 1;
            #pragma unroll
            for (int p = 0; p < 2; p++){
                float hv[2];
                #pragma unroll
                for (int e = 0; e < 2; e++){
                    float gi = acc[0][p*2+e] + bias[0][e];
                    float gf = acc[1][p*2+e] + bias[1][e];
                    float gg = acc[2][p*2+e] + bias[2][e];
                    float go = acc[3][p*2+e] + bias[3][e];
                    if (!ENC && t == 0){
                        gi -= corr[p][0][e]; gf -= corr[p][1][e];
                        gg -= corr[p][2][e]; go -= corr[p][3][e];
                    }
                    float cn = sigf(gf)*cst[p][e] + sigf(gi)*tanh_f(gg);
                    cst[p][e] = cn;
                    hv[e] = sigf(go)*tanh_f(cn);
                }
                int r = rbase + p*8;
                __half h0 = __float2half_rn(hv[0]);
                __half h1 = __float2half_rn(hv[1]);
                uint32_t uh = (uint32_t)__half_as_ushort(h0) | ((uint32_t)__half_as_ushort(h1) << 16);
                *(uint32_t*)&g_h16[nimg][(size_t)r*HH + j0w + jj] = uh;
                if (ENC){
                    if (t == TT-1){
                        g_hA[(size_t)r*HH + j0w + jj]     = hv[0];
                        g_hA[(size_t)r*HH + j0w + jj + 1] = hv[1];
                    }
                } else {
                    float2 f2; f2.x = hv[0]; f2.y = hv[1];
                    *(float2*)&g_Hbuf[((size_t)t*BB + r)*HH + j0w + jj] = f2;
                }
            }
        }
        if (ENC && t + 1 < TT) stage(0, 0, t+1);   // x(t+1) across the barrier
        grid_sync((unsigned)t);
    }
}

// ---------------- VQ ----------------
__global__ void k_vq(const float* __restrict__ emb){
    int b = blockIdx.x, tid = threadIdx.x;
    __shared__ float zs[HH];
    __shared__ float rs[256];
    __shared__ int   rk[256];
    zs[tid]       = g_hA[(size_t)b*HH + tid];
    zs[tid + 256] = g_hA[(size_t)b*HH + tid + 256];
    __syncthreads();
    float bestS = 3.4e38f; int bestK = 0;
    #pragma unroll
    for (int kq = 0; kq < 2; kq++){
        int k = tid + kq*256;
        const float* e = emb + (size_t)k*HH;
        float s = 0.f, dt = 0.f;
        for (int jj = 0; jj < HH; jj++){ float ev = e[jj]; s += ev*ev; dt += ev*zs[jj]; }
        float score = s - 2.f*dt;
        if (score < bestS || (score == bestS && k < bestK)){ bestS = score; bestK = k; }
    }
    rs[tid] = bestS; rk[tid] = bestK;
    __syncthreads();
    for (int s = 128; s > 0; s >>= 1){
        if (tid < s){
            if (rs[tid+s] < rs[tid] || (rs[tid+s] == rs[tid] && rk[tid+s] < rk[tid])){
                rs[tid] = rs[tid+s]; rk[tid] = rk[tid+s];
            }
        }
        __syncthreads();
    }
    int idx = rk[0];
    if (tid == 0) g_idx[b] = idx;
    float lp = 0.f;
    #pragma unroll
    for (int kq = 0; kq < 2; kq++){
        int jj = tid + kq*256;
        float q = emb[(size_t)idx*HH + jj];
        g_quant[(size_t)b*HH + jj] = q;
        float dz = q - zs[jj];
        lp += dz*dz;
    }
    __syncthreads();
    rs[tid] = lp;
    __syncthreads();
    for (int s = 128; s > 0; s >>= 1){
        if (tid < s) rs[tid] += rs[tid+s];
        __syncthreads();
    }
    if (tid == 0) g_lossp[b] = rs[0];
}

__global__ void k_vqfinish(float* __restrict__ out){
    const size_t OFF = (size_t)BB*TT*DD;
    int tid = threadIdx.x;
    if (tid == 0){
        float tot = 0.f;
        for (int i = 0; i < BB; i++) tot += g_lossp[i];
        out[OFF] = 1.25f * tot / (float)(BB*HH);
    }
    out[OFF + 1 + tid] = (float)g_idx[tid];
}

// ---------------- recon head ----------------
__device__ __forceinline__ void stage_h32r(float hsb[32][68], const float* __restrict__ src, int stride){
    int kk = threadIdx.x & 31, rb = threadIdx.x >> 5;
    #pragma unroll
    for (int i = 0; i < 8; i++)
        hsb[kk][rb + i*8] = src[(size_t)(rb + i*8)*stride + kk];
}

__global__ void __launch_bounds__(256) k_recon(const float* __restrict__ fcW,
                                               const float* __restrict__ fcb,
                                               float* __restrict__ out){
    __shared__ __align__(16) float hsb[32][68];
    __shared__ unsigned long long wsd[32][DD];
    int t = blockIdx.x;
    int b0 = blockIdx.y * 64;
    int tid = threadIdx.x;
    int txd = tid & 15, tyb = tid >> 4;

    unsigned long long acc[5][2];
    #pragma unroll
    for (int s = 0; s < 5; s++){ acc[s][0] = 0ull; acc[s][1] = 0ull; }

    for (int c = 0; c < 16; c++){
        __syncthreads();
        stage_h32r(hsb, g_Hbuf + ((size_t)t*BB + b0)*HH + c*32, HH);
        {
            int kk = tid & 31, db = tid >> 5;
            #pragma unroll
            for (int i = 0; i < 10; i++){
                int d = db + i*8;
                wsd[kk][d] = dupf(fcW[(size_t)d*HH + c*32 + kk]);
            }
        }
        __syncthreads();
        #pragma unroll
        for (int kk = 0; kk < 32; kk++){
            ulonglong2 hp = *(const ulonglong2*)&hsb[kk][tyb*4];
            #pragma unroll
            for (int s = 0; s < 5; s++){
                unsigned long long w = wsd[kk][txd + 16*s];
                ffma2(acc[s][0], hp.x, w);
                ffma2(acc[s][1], hp.y, w);
            }
        }
    }
    #pragma unroll
    for (int s = 0; s < 5; s++){
        int d = txd + 16*s;
        float bv = fcb[d];
        #pragma unroll
        for (int p = 0; p < 2; p++){
            float2 v = ull2f(acc[s][p]);
            int b = b0 + tyb*4 + p*2;
            out[((size_t)b*TT + t)*DD + d]     = v.x + bv;
            out[((size_t)(b+1)*TT + t)*DD + d] = v.y + bv;
        }
    }
}

// ---------------- launcher ----------------
extern "C" void kernel_launch(void* const* d_in, const int* in_sizes, int n_in,
                              void* d_out, int out_size){
    (void)in_sizes; (void)n_in; (void)out_size;
    const float* traj = (const float*)d_in[0];
    const float* eWih = (const float*)d_in[2];
    const float* eWhh = (const float*)d_in[3];
    const float* ebi  = (const float*)d_in[4];
    const float* ebh  = (const float*)d_in[5];
    const float* emb  = (const float*)d_in[6];
    const float* dWih = (const float*)d_in[7];
    const float* dWhh = (const float*)d_in[8];
    const float* dbi  = (const float*)d_in[9];
    const float* dbh  = (const float*)d_in[10];
    const float* fcW  = (const float*)d_in[11];
    const float* fcb  = (const float*)d_in[12];
    float* out = (float*)d_out;

    const int SME = (64*600 + 3*32*CS)*2;   // 102912 B
    const int SMD = (64*520 + 3*32*CS)*2;   //  92672 B
    cudaFuncSetAttribute(k_rnn<true>,  cudaFuncAttributeMaxDynamicSharedMemorySize, SME);
    cudaFuncSetAttribute(k_rnn<false>, cudaFuncAttributeMaxDynamicSharedMemorySize, SMD);

    k_bias<<<8, 256>>>(ebi, ebh, dbi, dbh, dWih, fcb);
    k_wcomb<<<512, 256>>>(dWih, dWhh, fcW);
    k_tx<<<1024, 256>>>(traj);
    k_rnn<true><<<NBLK, NTH, SME>>>(eWih, eWhh);   // 4th launch -> ncu capture slot
    k_vq<<<BB, 256>>>(emb);
    k_vqfinish<<<1, 256>>>(out);
    k_x1<<<BB, 256>>>(fcW, fcb);
    k_corr<<<GG, 256>>>(dWih);
    k_decprep<<<512, 256>>>();
    k_rnn<false><<<NBLK, NTH, SMD>>>(eWih, eWhh);
    k_recon<<<dim3(TT, 4), 256>>>(fcW, fcb, out);
}

// round 14
// speedup vs baseline: 1.6093x; 1.0422x over previous
#include <cuda_runtime.h>
#include <cuda_fp16.h>
#include <cstdint>

#define BB 256
#define TT 256
#define DD 80
#define HH 512
#define GG 2048
#define NBLK 256
#define NTH 128
#define CS 136                 // h chunk smem stride (halves)

// ---------------- device scratch ----------------
__device__ __align__(16) __half g_h16[2][(size_t)BB*HH]; // [parity]
__device__ __align__(16) __half g_txh[(size_t)BB*TT*DD];
__device__ float g_Wcomb[(size_t)GG*HH];
__device__ float g_bias_enc[GG];
__device__ float g_bcomb[GG];
__device__ float g_quant[BB*HH];
__device__ float g_hA[BB*HH];
__device__ float g_tmpT[DD*BB];
__device__ float g_corr[(size_t)BB*GG];
__device__ float g_lossp[BB];
__device__ int   g_idx[BB];
__device__ float g_Hbuf[(size_t)TT*BB*HH];
__device__ unsigned g_barE[8];
__device__ unsigned g_barD[8];

// ---------------- helpers ----------------
__device__ __forceinline__ unsigned long long dupf(float v){
    unsigned long long r; asm("mov.b64 %0, {%1,%1};" : "=l"(r) : "f"(v)); return r;
}
__device__ __forceinline__ float2 ull2f(unsigned long long v){
    float2 r; asm("mov.b64 {%0,%1}, %2;" : "=f"(r.x), "=f"(r.y) : "l"(v)); return r;
}
__device__ __forceinline__ void ffma2(unsigned long long& d, unsigned long long a, unsigned long long b){
    asm("fma.rn.f32x2 %0, %1, %2, %0;" : "+l"(d) : "l"(a), "l"(b));
}
__device__ __forceinline__ float sigf(float x){ return __fdividef(1.f, 1.f + __expf(-x)); }
__device__ __forceinline__ float tanh_f(float x){ return __fdividef(2.f, 1.f + __expf(-2.f*x)) - 1.f; }

__device__ __forceinline__ void cpa16s(uint32_t dst, const void* src){
    asm volatile("cp.async.cg.shared.global [%0], [%1], 16;" :: "r"(dst), "l"(src));
}
__device__ __forceinline__ void cpa_commit(){ asm volatile("cp.async.commit_group;" ::: "memory"); }
__device__ __forceinline__ void cpa_wait0(){ asm volatile("cp.async.wait_group 0;" ::: "memory"); }
__device__ __forceinline__ void cpa_wait1(){ asm volatile("cp.async.wait_group 1;" ::: "memory"); }

__device__ __forceinline__ void ldsm4(uint32_t* r, uint32_t addr){
    asm volatile("ldmatrix.sync.aligned.m8n8.x4.shared.b16 {%0,%1,%2,%3}, [%4];"
        : "=r"(r[0]), "=r"(r[1]), "=r"(r[2]), "=r"(r[3]) : "r"(addr));
}
__device__ __forceinline__ void hmma(float* c, const uint32_t* a, const uint32_t* b){
    asm volatile("mma.sync.aligned.m16n8k16.row.col.f32.f16.f16.f32 "
        "{%0,%1,%2,%3}, {%4,%5,%6,%7}, {%8,%9}, {%0,%1,%2,%3};"
        : "+f"(c[0]), "+f"(c[1]), "+f"(c[2]), "+f"(c[3])
        : "r"(a[0]), "r"(a[1]), "r"(a[2]), "r"(a[3]), "r"(b[0]), "r"(b[1]));
}

__device__ __forceinline__ void spin_ge(unsigned* p, unsigned tgt){
    unsigned v;
    do {
        asm volatile("ld.acquire.gpu.u32 %0, [%1];" : "=r"(v) : "l"(p) : "memory");
    } while (v < tgt);
}
__device__ __forceinline__ void post_flag(unsigned* p){
    asm volatile("red.release.gpu.global.add.u32 [%0], %1;" :: "l"(p), "r"(1u) : "memory");
}

// 1-term MMA over one chunk: acc[gate][4]
template<int NK, int SW>
__device__ __forceinline__ void mma_loop(float acc[4][4], uint32_t aA, uint32_t bH){
    #pragma unroll
    for (int kk = 0; kk < NK; kk++){
        uint32_t ah[4], bh0[4], bh1[4];
        ldsm4(ah,  aA + kk*32);
        ldsm4(bh0, bH + kk*32);
        ldsm4(bh1, bH + 16*SW*2 + kk*32);
        hmma(acc[0], ah, bh0);   hmma(acc[1], ah, bh0+2);
        hmma(acc[2], ah, bh1);   hmma(acc[3], ah, bh1+2);
    }
}

// ---------------- prep kernels ----------------
__global__ void k_bias(const float* __restrict__ ebi, const float* __restrict__ ebh,
                       const float* __restrict__ dbi, const float* __restrict__ dbh,
                       const float* __restrict__ dWih, const float* __restrict__ fcb){
    int n = blockIdx.x*blockDim.x + threadIdx.x;
    if (n < GG){
        g_bias_enc[n] = ebi[n] + ebh[n];
        float b = dbi[n] + dbh[n];
        const float* w = dWih + (size_t)n*DD;
        #pragma unroll 4
        for (int d = 0; d < DD; d++) b += fcb[d]*w[d];
        g_bcomb[n] = b;
    }
}

__global__ void k_wcomb(const float* __restrict__ dWih, const float* __restrict__ dWhh,
                        const float* __restrict__ fcW){
    __shared__ float sf[DD][64];
    __shared__ float sw[32][DD];
    int nt = blockIdx.x >> 3, kt = blockIdx.x & 7;
    int n0 = nt*32, k0 = kt*64;
    int tid = threadIdx.x;
    for (int idx = tid; idx < DD*64; idx += 256){
        int d = idx >> 6, kk = idx & 63;
        sf[d][kk] = fcW[(size_t)d*HH + k0 + kk];
    }
    for (int idx = tid; idx < 32*DD; idx += 256){
        int nn = idx / DD, d = idx % DD;
        sw[nn][d] = dWih[(size_t)(n0+nn)*DD + d];
    }
    __syncthreads();
    int nn = tid >> 3, kb = (tid & 7)*8;
    float a[8];
    #pragma unroll
    for (int i = 0; i < 8; i++) a[i] = dWhh[(size_t)(n0+nn)*HH + k0 + kb + i];
    for (int d = 0; d < DD; d++){
        float w = sw[nn][d];
        #pragma unroll
        for (int i = 0; i < 8; i++) a[i] += w * sf[d][kb+i];
    }
    #pragma unroll
    for (int i = 0; i < 8; i++) g_Wcomb[(size_t)(n0+nn)*HH + k0 + kb + i] = a[i];
}

__global__ void k_tx(const float* __restrict__ traj){
    if (blockIdx.x == 0 && threadIdx.x < 16){
        if (threadIdx.x < 8) g_barE[threadIdx.x] = 0u;
        else                 g_barD[threadIdx.x - 8] = 0u;
    }
    size_t N = (size_t)BB*TT*DD;
    for (size_t i = (size_t)blockIdx.x*blockDim.x + threadIdx.x; i < N; i += (size_t)gridDim.x*blockDim.x)
        g_txh[i] = __float2half_rn(traj[i]);
}

__global__ void k_x1(const float* __restrict__ fcW, const float* __restrict__ fcb){
    int b = blockIdx.x, tid = threadIdx.x;
    __shared__ float qs[HH];
    qs[tid]       = g_quant[(size_t)b*HH + tid];
    qs[tid + 256] = g_quant[(size_t)b*HH + tid + 256];
    __syncthreads();
    if (tid < DD){
        const float* w = fcW + (size_t)tid*HH;
        float s = fcb[tid];
        for (int k = 0; k < HH; k++) s += w[k]*qs[k];
        g_tmpT[tid*BB + b] = s;
    }
}

__global__ void k_corr(const float* __restrict__ dWih){
    int n = blockIdx.x, b = threadIdx.x;
    __shared__ float wd[DD];
    if (b < DD) wd[b] = dWih[(size_t)n*DD + b];
    __syncthreads();
    float s = 0.f;
    #pragma unroll 4
    for (int d = 0; d < DD; d++) s += wd[d] * g_tmpT[d*BB + b];
    g_corr[(size_t)b*GG + n] = s;
}

__global__ void k_decprep(){
    int i = blockIdx.x*blockDim.x + threadIdx.x;
    if (i < BB*HH) g_h16[0][i] = __float2half_rn(g_quant[i]);
}

// ---------------- persistent recurrent kernel ----------------
// Block: 32 batch rows x 64 gate-cols (16 j x 4 gates). 4 warps = 2M x 2N.
// Grid 256 = 8 rowgroups x 32 colgroups; 2 CTAs/SM.
// Sync: per-rowgroup release/acquire counter (32 arrivals/step); arrive after
// h publish, secondary writes between arrive and next wait.
template<bool ENC>
__global__ void __launch_bounds__(NTH, 2) k_rnn(const float* __restrict__ eWih,
                                                const float* __restrict__ eWhh){
    extern __shared__ __half smh[];
    constexpr int SW = ENC ? 600 : 520;
    constexpr int KW = ENC ? 592 : 512;
    constexpr int NC = ENC ? 5 : 4;
    const uint32_t WREG = (uint32_t)(64*SW*2);           // bytes for W
    const uint32_t HS_OFF = WREG;
    const uint32_t BUFB = (uint32_t)(32*CS*2);

    const int tid = threadIdx.x;
    const int wid = tid >> 5, lane = tid & 31;
    const int wm = wid & 1, wn = wid >> 1;
    const int rg = blockIdx.x >> 5, cg = blockIdx.x & 31;
    const int row0 = rg*32, j0 = cg*16;
    const uint32_t smb = (uint32_t)__cvta_generic_to_shared(smh);
    unsigned* bar = (ENC ? g_barE : g_barD) + rg;

    // ---- W fill (hi only): 64 B-rows x KW ----
    for (int idx = tid; idx < 64*KW; idx += NTH){
        int br = idx / KW, k = idx - br*KW;
        int n = ((br >> 3) & 3)*HH + j0 + (br >> 5)*8 + (br & 7);
        float v;
        if (ENC) v = (k < HH) ? eWhh[(size_t)n*HH + k] : eWih[(size_t)n*DD + k - HH];
        else     v = g_Wcomb[(size_t)n*HH + k];
        smh[br*SW + k] = __float2half_rn(v);
    }

    const int j0w = j0 + wn*8;
    const int jj = (lane & 3)*2;
    const int rbase = row0 + wm*16 + (lane >> 2);
    float bias[4][2], corr[2][4][2];
    #pragma unroll
    for (int q = 0; q < 4; q++)
        #pragma unroll
        for (int e = 0; e < 2; e++){
            bias[q][e] = ENC ? g_bias_enc[q*HH + j0w + jj + e] : g_bcomb[q*HH + j0w + jj + e];
            if (!ENC){
                corr[0][q][e] = g_corr[(size_t)rbase*GG + q*HH + j0w + jj + e];
                corr[1][q][e] = g_corr[(size_t)(rbase+8)*GG + q*HH + j0w + jj + e];
            }
        }
    float cst[2][2] = {{0.f,0.f},{0.f,0.f}};

    const uint32_t laneA = (uint32_t)((wm*16 + (lane & 15))*CS + (lane >> 4)*8)*2;
    const uint32_t laneB = (uint32_t)(((lane & 7) + ((lane >> 4) & 1)*8 + wn*32)*SW + ((lane >> 3) & 1)*8)*2;

    // stage chunk c of step t into buffer buf (32 rows)
    auto stage = [&](int buf, int c, int t){
        uint32_t dst = smb + HS_OFF + (uint32_t)buf*BUFB;
        if (ENC && c == 0){
            #pragma unroll
            for (int i = 0; i < 3; i++){
                int u = tid + i*NTH;
                if (u < 320){
                    int r = u/10, s = u - r*10;
                    cpa16s(dst + (uint32_t)(r*CS*2 + s*16),
                           g_txh + ((size_t)(row0+r)*TT + t)*DD + s*8);
                }
            }
        } else {
            const __half* src = g_h16[t & 1];
            int kb = ENC ? (c-1)*128 : c*128;
            #pragma unroll
            for (int i = 0; i < 4; i++){
                int u = tid + i*NTH;
                int r = u >> 4, s = u & 15;
                cpa16s(dst + (uint32_t)(r*CS*2 + s*16),
                       src + (size_t)(row0+r)*HH + kb + s*8);
            }
        }
        cpa_commit();
    };

    __syncthreads();
    if (ENC) stage(0, 0, 0);   // x(0), no h dependency

    for (int t = 0; t < TT; t++){
        // ---- wait for rowgroup producers of h(t) ----
        if (t > 0){
            if (tid == 0) spin_ge(bar, 32u*(unsigned)t);
            __syncthreads();
        }
        if (!ENC) stage(0, 0, t);
        const int nc = (ENC && t == 0) ? 1 : NC;
        if (nc > 1) stage(1, 1, t);

        float acc[4][4];
        #pragma unroll
        for (int q = 0; q < 4; q++)
            #pragma unroll
            for (int i = 0; i < 4; i++) acc[q][i] = 0.f;

        for (int c = 0; c < nc; c++){
            if (c < nc-1) cpa_wait1(); else cpa_wait0();
            __syncthreads();
            if (c + 2 < nc) stage((c+2)%3, c+2, t);
            {
                uint32_t aA = smb + HS_OFF + (uint32_t)(c%3)*BUFB + laneA;
                int koff = (ENC && c == 0) ? 512 : (ENC ? (c-1)*128 : c*128);
                uint32_t bH = smb + laneB + (uint32_t)koff*2;
                if (ENC && c == 0) mma_loop<5, SW>(acc, aA, bH);
                else               mma_loop<8, SW>(acc, aA, bH);
            }
        }

        // ---- epilogue: compute + publish h(t+1), arrive, then secondary writes ----
        const int nimg = (t+1) & 1;
        float hvs[2][2];
        #pragma unroll
        for (int p = 0; p < 2; p++){
            #pragma unroll
            for (int e = 0; e < 2; e++){
                float gi = acc[0][p*2+e] + bias[0][e];
                float gf = acc[1][p*2+e] + bias[1][e];
                float gg = acc[2][p*2+e] + bias[2][e];
                float go = acc[3][p*2+e] + bias[3][e];
                if (!ENC && t == 0){
                    gi -= corr[p][0][e]; gf -= corr[p][1][e];
                    gg -= corr[p][2][e]; go -= corr[p][3][e];
                }
                float cn = sigf(gf)*cst[p][e] + sigf(gi)*tanh_f(gg);
                cst[p][e] = cn;
                hvs[p][e] = sigf(go)*tanh_f(cn);
            }
            int r = rbase + p*8;
            __half h0 = __float2half_rn(hvs[p][0]);
            __half h1 = __float2half_rn(hvs[p][1]);
            uint32_t uh = (uint32_t)__half_as_ushort(h0) | ((uint32_t)__half_as_ushort(h1) << 16);
            *(uint32_t*)&g_h16[nimg][(size_t)r*HH + j0w + jj] = uh;
        }
        __syncthreads();
        if (tid == 0) post_flag(bar);

        // secondary outputs + enc x-prefetch: off the inter-block critical path
        #pragma unroll
        for (int p = 0; p < 2; p++){
            int r = rbase + p*8;
            if (ENC){
                if (t == TT-1){
                    g_hA[(size_t)r*HH + j0w + jj]     = hvs[p][0];
                    g_hA[(size_t)r*HH + j0w + jj + 1] = hvs[p][1];
                }
            } else {
                float2 f2; f2.x = hvs[p][0]; f2.y = hvs[p][1];
                *(float2*)&g_Hbuf[((size_t)t*BB + r)*HH + j0w + jj] = f2;
            }
        }
        if (ENC && t + 1 < TT) stage(0, 0, t+1);   // x(t+1)
    }
}

// ---------------- VQ ----------------
__global__ void k_vq(const float* __restrict__ emb){
    int b = blockIdx.x, tid = threadIdx.x;
    __shared__ float zs[HH];
    __shared__ float rs[256];
    __shared__ int   rk[256];
    zs[tid]       = g_hA[(size_t)b*HH + tid];
    zs[tid + 256] = g_hA[(size_t)b*HH + tid + 256];
    __syncthreads();
    float bestS = 3.4e38f; int bestK = 0;
    #pragma unroll
    for (int kq = 0; kq < 2; kq++){
        int k = tid + kq*256;
        const float* e = emb + (size_t)k*HH;
        float s = 0.f, dt = 0.f;
        for (int jj = 0; jj < HH; jj++){ float ev = e[jj]; s += ev*ev; dt += ev*zs[jj]; }
        float score = s - 2.f*dt;
        if (score < bestS || (score == bestS && k < bestK)){ bestS = score; bestK = k; }
    }
    rs[tid] = bestS; rk[tid] = bestK;
    __syncthreads();
    for (int s = 128; s > 0; s >>= 1){
        if (tid < s){
            if (rs[tid+s] < rs[tid] || (rs[tid+s] == rs[tid] && rk[tid+s] < rk[tid])){
                rs[tid] = rs[tid+s]; rk[tid] = rk[tid+s];
            }
        }
        __syncthreads();
    }
    int idx = rk[0];
    if (tid == 0) g_idx[b] = idx;
    float lp = 0.f;
    #pragma unroll
    for (int kq = 0; kq < 2; kq++){
        int jj = tid + kq*256;
        float q = emb[(size_t)idx*HH + jj];
        g_quant[(size_t)b*HH + jj] = q;
        float dz = q - zs[jj];
        lp += dz*dz;
    }
    __syncthreads();
    rs[tid] = lp;
    __syncthreads();
    for (int s = 128; s > 0; s >>= 1){
        if (tid < s) rs[tid] += rs[tid+s];
        __syncthreads();
    }
    if (tid == 0) g_lossp[b] = rs[0];
}

__global__ void k_vqfinish(float* __restrict__ out){
    const size_t OFF = (size_t)BB*TT*DD;
    int tid = threadIdx.x;
    if (tid == 0){
        float tot = 0.f;
        for (int i = 0; i < BB; i++) tot += g_lossp[i];
        out[OFF] = 1.25f * tot / (float)(BB*HH);
    }
    out[OFF + 1 + tid] = (float)g_idx[tid];
}

// ---------------- recon head ----------------
__device__ __forceinline__ void stage_h32r(float hsb[32][68], const float* __restrict__ src, int stride){
    int kk = threadIdx.x & 31, rb = threadIdx.x >> 5;
    #pragma unroll
    for (int i = 0; i < 8; i++)
        hsb[kk][rb + i*8] = src[(size_t)(rb + i*8)*stride + kk];
}

__global__ void __launch_bounds__(256) k_recon(const float* __restrict__ fcW,
                                               const float* __restrict__ fcb,
                                               float* __restrict__ out){
    __shared__ __align__(16) float hsb[32][68];
    __shared__ unsigned long long wsd[32][DD];
    int t = blockIdx.x;
    int b0 = blockIdx.y * 64;
    int tid = threadIdx.x;
    int txd = tid & 15, tyb = tid >> 4;

    unsigned long long acc[5][2];
    #pragma unroll
    for (int s = 0; s < 5; s++){ acc[s][0] = 0ull; acc[s][1] = 0ull; }

    for (int c = 0; c < 16; c++){
        __syncthreads();
        stage_h32r(hsb, g_Hbuf + ((size_t)t*BB + b0)*HH + c*32, HH);
        {
            int kk = tid & 31, db = tid >> 5;
            #pragma unroll
            for (int i = 0; i < 10; i++){
                int d = db + i*8;
                wsd[kk][d] = dupf(fcW[(size_t)d*HH + c*32 + kk]);
            }
        }
        __syncthreads();
        #pragma unroll
        for (int kk = 0; kk < 32; kk++){
            ulonglong2 hp = *(const ulonglong2*)&hsb[kk][tyb*4];
            #pragma unroll
            for (int s = 0; s < 5; s++){
                unsigned long long w = wsd[kk][txd + 16*s];
                ffma2(acc[s][0], hp.x, w);
                ffma2(acc[s][1], hp.y, w);
            }
        }
    }
    #pragma unroll
    for (int s = 0; s < 5; s++){
        int d = txd + 16*s;
        float bv = fcb[d];
        #pragma unroll
        for (int p = 0; p < 2; p++){
            float2 v = ull2f(acc[s][p]);
            int b = b0 + tyb*4 + p*2;
            out[((size_t)b*TT + t)*DD + d]     = v.x + bv;
            out[((size_t)(b+1)*TT + t)*DD + d] = v.y + bv;
        }
    }
}

// ---------------- launcher ----------------
extern "C" void kernel_launch(void* const* d_in, const int* in_sizes, int n_in,
                              void* d_out, int out_size){
    (void)in_sizes; (void)n_in; (void)out_size;
    const float* traj = (const float*)d_in[0];
    const float* eWih = (const float*)d_in[2];
    const float* eWhh = (const float*)d_in[3];
    const float* ebi  = (const float*)d_in[4];
    const float* ebh  = (const float*)d_in[5];
    const float* emb  = (const float*)d_in[6];
    const float* dWih = (const float*)d_in[7];
    const float* dWhh = (const float*)d_in[8];
    const float* dbi  = (const float*)d_in[9];
    const float* dbh  = (const float*)d_in[10];
    const float* fcW  = (const float*)d_in[11];
    const float* fcb  = (const float*)d_in[12];
    float* out = (float*)d_out;

    const int SME = (64*600 + 3*32*CS)*2;   // 102912 B
    const int SMD = (64*520 + 3*32*CS)*2;   //  92672 B
    cudaFuncSetAttribute(k_rnn<true>,  cudaFuncAttributeMaxDynamicSharedMemorySize, SME);
    cudaFuncSetAttribute(k_rnn<false>, cudaFuncAttributeMaxDynamicSharedMemorySize, SMD);

    k_bias<<<8, 256>>>(ebi, ebh, dbi, dbh, dWih, fcb);
    k_wcomb<<<512, 256>>>(dWih, dWhh, fcW);
    k_tx<<<1024, 256>>>(traj);
    k_rnn<true><<<NBLK, NTH, SME>>>(eWih, eWhh);   // 4th launch -> ncu capture slot
    k_vq<<<BB, 256>>>(emb);
    k_vqfinish<<<1, 256>>>(out);
    k_x1<<<BB, 256>>>(fcW, fcb);
    k_corr<<<GG, 256>>>(dWih);
    k_decprep<<<512, 256>>>();
    k_rnn<false><<<NBLK, NTH, SMD>>>(eWih, eWhh);
    k_recon<<<dim3(TT, 4), 256>>>(fcW, fcb, out);
}